// round 6
// baseline (speedup 1.0000x reference)
#include <cuda_runtime.h>
#include <cuda_fp16.h>
#include <math.h>

#define NN 20000
#define EE 320000
#define ET 340000      // EE + NN self loops
#define FIN 128
#define D1 512         // HEADS*HID
#define HEADS 8
#define HID 64
#define NC 10
#define NG 64

// -------- scratch (device globals; no allocations allowed) --------
__device__ __half g_h1h[(size_t)NN * D1];    // layer1 features, fp16 (gathered by agg1)
__device__ float g_h1act[(size_t)NN * D1];   // elu(agg1 + b1)
__device__ float g_asrc1[NN * HEADS];
__device__ float g_adst1[NN * HEADS];
__device__ float g_h2[NN * NC];
__device__ float g_asrc2[NN];
__device__ float g_adst2[NN];
__device__ float g_agg2[NN * NC];
__device__ int   g_counts[NN];
__device__ int   g_rowptr[NN + 1];
__device__ int   g_wptr[NN];
__device__ int   g_csrc[ET];

__device__ __forceinline__ float wredsum(float v) {
    #pragma unroll
    for (int o = 16; o; o >>= 1) v += __shfl_xor_sync(0xffffffffu, v, o);
    return v;
}

// -------- CSR build --------
// counts start at 1: self-loop pre-counted; its slot is filled in scan.
__global__ void init_counts_kernel() {
    int i = blockIdx.x * blockDim.x + threadIdx.x;
    if (i < NN) g_counts[i] = 1;
}

// ILP-4: int4 loads, 4 outstanding atomics per thread
__global__ void count_kernel(const int* __restrict__ ei) {
    int i = blockIdx.x * blockDim.x + threadIdx.x;
    if (i >= EE / 4) return;
    int4 d = ((const int4*)(ei + EE))[i];
    atomicAdd(&g_counts[d.x], 1);
    atomicAdd(&g_counts[d.y], 1);
    atomicAdd(&g_counts[d.z], 1);
    atomicAdd(&g_counts[d.w], 1);
}

__global__ void scan_kernel() {
    __shared__ int sh[1024];
    int t = threadIdx.x;
    const int CH = (NN + 1023) / 1024;
    int base = t * CH;
    int s = 0;
    for (int i = 0; i < CH; i++) {
        int idx = base + i;
        if (idx < NN) s += g_counts[idx];
    }
    sh[t] = s;
    __syncthreads();
    for (int off = 1; off < 1024; off <<= 1) {
        int v = (t >= off) ? sh[t - off] : 0;
        __syncthreads();
        sh[t] += v;
        __syncthreads();
    }
    int run = sh[t] - s;
    for (int i = 0; i < CH; i++) {
        int idx = base + i;
        if (idx < NN) {
            g_rowptr[idx] = run;
            g_csrc[run]   = idx;      // self-loop occupies first slot
            g_wptr[idx]   = run + 1;  // real edges start after it
            run += g_counts[idx];
        }
    }
    if (t == 1023) g_rowptr[NN] = sh[1023];
}

__global__ void scatter_kernel(const int* __restrict__ ei) {
    int i = blockIdx.x * blockDim.x + threadIdx.x;
    if (i >= EE / 4) return;
    int4 s = ((const int4*)ei)[i];
    int4 d = ((const int4*)(ei + EE))[i];
    int p0 = atomicAdd(&g_wptr[d.x], 1);
    int p1 = atomicAdd(&g_wptr[d.y], 1);
    int p2 = atomicAdd(&g_wptr[d.z], 1);
    int p3 = atomicAdd(&g_wptr[d.w], 1);
    g_csrc[p0] = s.x;
    g_csrc[p1] = s.y;
    g_csrc[p2] = s.z;
    g_csrc[p3] = s.w;
}

// -------- GEMM1 + fused layer-1 attention coefficients --------
// h1 (fp16) = x @ W1; per-head coefs via 16-lane shuffle reduce (fp32).
__global__ void gemm1_kernel(const float* __restrict__ X,
                             const float* __restrict__ W,
                             const float* __restrict__ asv,
                             const float* __restrict__ adv) {
    __shared__ float As[64][68];   // [k][m]
    __shared__ float Bs[64][64];   // [k][n]
    __shared__ float sa[64], sd[64];
    int t = threadIdx.x;
    int m0 = blockIdx.y * 64, n0 = blockIdx.x * 64;
    if (t < 64) { sa[t] = asv[n0 + t]; sd[t] = adv[n0 + t]; }
    int tm = (t >> 4) << 2;        // 0..60
    int tn = (t & 15) << 2;        // 0..60
    float acc[4][4];
    #pragma unroll
    for (int i = 0; i < 4; i++)
        #pragma unroll
        for (int j = 0; j < 4; j++) acc[i][j] = 0.f;

    for (int k0 = 0; k0 < FIN; k0 += 64) {
        int kk = t & 63;
        #pragma unroll
        for (int p = 0; p < 16; p++) {
            int rr = (t >> 6) + p * 4;
            int row = m0 + rr;
            float v = (row < NN) ? X[(size_t)row * FIN + k0 + kk] : 0.f;
            As[kk][rr] = v;
        }
        #pragma unroll
        for (int p = 0; p < 4; p++) {
            int id = t + p * 256;
            int bk = id >> 4, nv = id & 15;
            float4 v = *(const float4*)&W[(size_t)(k0 + bk) * D1 + n0 + (nv << 2)];
            *(float4*)&Bs[bk][nv << 2] = v;
        }
        __syncthreads();
        #pragma unroll 16
        for (int k = 0; k < 64; k++) {
            float4 a = *(const float4*)&As[k][tm];
            float4 b = *(const float4*)&Bs[k][tn];
            acc[0][0] += a.x * b.x; acc[0][1] += a.x * b.y; acc[0][2] += a.x * b.z; acc[0][3] += a.x * b.w;
            acc[1][0] += a.y * b.x; acc[1][1] += a.y * b.y; acc[1][2] += a.y * b.z; acc[1][3] += a.y * b.w;
            acc[2][0] += a.z * b.x; acc[2][1] += a.z * b.y; acc[2][2] += a.z * b.z; acc[2][3] += a.z * b.w;
            acc[3][0] += a.w * b.x; acc[3][1] += a.w * b.y; acc[3][2] += a.w * b.z; acc[3][3] += a.w * b.w;
        }
        __syncthreads();
    }
    int h = n0 >> 6;
    #pragma unroll
    for (int i = 0; i < 4; i++) {
        int row = m0 + tm + i;
        if (row < NN) {
            union { __half2 h2[2]; uint2 u; } pk;
            pk.h2[0] = __floats2half2_rn(acc[i][0], acc[i][1]);
            pk.h2[1] = __floats2half2_rn(acc[i][2], acc[i][3]);
            *(uint2*)&g_h1h[(size_t)row * D1 + n0 + tn] = pk.u;
        }
        float s = acc[i][0] * sa[tn]     + acc[i][1] * sa[tn + 1]
                + acc[i][2] * sa[tn + 2] + acc[i][3] * sa[tn + 3];
        float dd = acc[i][0] * sd[tn]     + acc[i][1] * sd[tn + 1]
                 + acc[i][2] * sd[tn + 2] + acc[i][3] * sd[tn + 3];
        #pragma unroll
        for (int o = 8; o >= 1; o >>= 1) {
            s  += __shfl_xor_sync(0xffffffffu, s, o);
            dd += __shfl_xor_sync(0xffffffffu, dd, o);
        }
        if ((t & 15) == 0 && row < NN) {
            g_asrc1[row * 8 + h] = s;
            g_adst1[row * 8 + h] = dd;
        }
    }
}

// -------- layer-1 edge softmax + aggregation: one block / dst node --------
// Single pass; thread t owns channels 4t..4t+3 (head h4 = t>>4).
// Gather fp16 rows: one LDG.64 per edge per thread (1 KB/edge total).
__global__ void agg1_kernel(const float* __restrict__ b1) {
    int d = blockIdx.x;
    int t = threadIdx.x;   // 128
    __shared__ float sadst[8], salpha[128], sinv[8];
    __shared__ int ssrc[16];
    int beg = g_rowptr[d];
    int deg = g_rowptr[d + 1] - beg;
    if (t < 8) sadst[t] = g_adst1[d * 8 + t];
    int h4 = t >> 4;
    float4 acc = make_float4(0.f, 0.f, 0.f, 0.f);
    float wpart = 0.f;

    for (int base = 0; base < deg; base += 16) {
        int cn = min(16, deg - base);
        __syncthreads();
        if (t < cn) ssrc[t] = g_csrc[beg + base + t];
        if (t < cn * 8) {
            int i = t >> 3, h = t & 7;
            float e = g_asrc1[g_csrc[beg + base + i] * 8 + h] + sadst[h];
            e = e > 0.f ? e : 0.2f * e;
            float w = __expf(e);
            salpha[t] = w;
            wpart += w;
        }
        __syncthreads();
        #pragma unroll 4
        for (int i = 0; i < cn; i++) {
            float a = salpha[i * 8 + h4];
            uint2 raw = *(const uint2*)&g_h1h[(size_t)ssrc[i] * D1 + 4 * t];
            float2 f0 = __half22float2(*(__half2*)&raw.x);
            float2 f1 = __half22float2(*(__half2*)&raw.y);
            acc.x += a * f0.x; acc.y += a * f0.y;
            acc.z += a * f1.x; acc.w += a * f1.y;
        }
    }
    __syncthreads();
    salpha[t] = wpart;
    __syncthreads();
    if (t < 8) {
        float s = 0.f;
        #pragma unroll
        for (int j = 0; j < 16; j++) s += salpha[t + 8 * j];
        sinv[t] = 1.f / (s + 1e-16f);
    }
    __syncthreads();
    float inv = sinv[h4];
    float4 bv = *(const float4*)&b1[4 * t];
    float4 o;
    o.x = acc.x * inv + bv.x; o.x = o.x > 0.f ? o.x : expm1f(o.x);
    o.y = acc.y * inv + bv.y; o.y = o.y > 0.f ? o.y : expm1f(o.y);
    o.z = acc.z * inv + bv.z; o.z = o.z > 0.f ? o.z : expm1f(o.z);
    o.w = acc.w * inv + bv.w; o.w = o.w > 0.f ? o.w : expm1f(o.w);
    *(float4*)&g_h1act[(size_t)d * D1 + 4 * t] = o;
}

// -------- layer 2 GEMV + coefficients (warp per node, transposed W2 smem) --------
__global__ void node2_kernel(const float* __restrict__ W2,
                             const float* __restrict__ as2,
                             const float* __restrict__ ad2) {
    __shared__ float Ws[NC * D1];   // [j][c] transposed, 20 KB
    __shared__ float sas[NC], sad[NC];
    int t = threadIdx.x;
    for (int i = t; i < D1 * NC; i += 256) {
        int c = i / NC, j = i - c * NC;
        Ws[j * D1 + c] = W2[i];
    }
    if (t < NC) { sas[t] = as2[t]; sad[t] = ad2[t]; }
    __syncthreads();
    int n = blockIdx.x * 8 + (t >> 5);
    if (n >= NN) return;
    int lane = t & 31;
    const float* hp = &g_h1act[(size_t)n * D1];
    float acc[NC];
    #pragma unroll
    for (int j = 0; j < NC; j++) acc[j] = 0.f;
    for (int c = lane; c < D1; c += 32) {
        float xv = hp[c];
        #pragma unroll
        for (int j = 0; j < NC; j++) acc[j] += xv * Ws[j * D1 + c];
    }
    #pragma unroll
    for (int j = 0; j < NC; j++) acc[j] = wredsum(acc[j]);
    if (lane == 0) {
        float s = 0.f, dd = 0.f;
        #pragma unroll
        for (int j = 0; j < NC; j++) {
            g_h2[n * NC + j] = acc[j];
            s  += acc[j] * sas[j];
            dd += acc[j] * sad[j];
        }
        g_asrc2[n] = s;
        g_adst2[n] = dd;
    }
}

// -------- layer-2 edge softmax + aggregation (warp per dst, single pass) --------
__global__ void agg2_kernel(const float* __restrict__ b2) {
    int n = blockIdx.x * 8 + (threadIdx.x >> 5);
    if (n >= NN) return;
    int lane = threadIdx.x & 31;
    int beg = g_rowptr[n], end = g_rowptr[n + 1];
    float adv = g_adst2[n];
    float s = 0.f;
    float acc[NC];
    #pragma unroll
    for (int j = 0; j < NC; j++) acc[j] = 0.f;
    for (int i = beg + lane; i < end; i += 32) {
        int sn = g_csrc[i];
        float e = g_asrc2[sn] + adv;
        e = e > 0.f ? e : 0.2f * e;
        float w = __expf(e);
        s += w;
        const float* hp = &g_h2[sn * NC];
        #pragma unroll
        for (int j = 0; j < NC; j++) acc[j] += w * hp[j];
    }
    s = wredsum(s);
    #pragma unroll
    for (int j = 0; j < NC; j++) acc[j] = wredsum(acc[j]);
    if (lane == 0) {
        float inv = 1.f / (s + 1e-16f);
        #pragma unroll
        for (int j = 0; j < NC; j++)
            g_agg2[n * NC + j] = acc[j] * inv + b2[j];
    }
}

// -------- mean pooling per graph (batch is sorted) --------
__global__ void pool_kernel(const int* __restrict__ batch,
                            float* __restrict__ out) {
    int g = blockIdx.x;
    int t = threadIdx.x;
    int lo, hi;
    { int a = 0, b = NN;
      while (a < b) { int mid = (a + b) >> 1; if (batch[mid] < g) a = mid + 1; else b = mid; }
      lo = a; }
    { int a = lo, b = NN;
      while (a < b) { int mid = (a + b) >> 1; if (batch[mid] < g + 1) a = mid + 1; else b = mid; }
      hi = a; }
    __shared__ float red[NC];
    if (t < NC) red[t] = 0.f;
    __syncthreads();
    float acc[NC];
    #pragma unroll
    for (int j = 0; j < NC; j++) acc[j] = 0.f;
    for (int i = lo + t; i < hi; i += 256) {
        const float* hp = &g_agg2[i * NC];
        #pragma unroll
        for (int j = 0; j < NC; j++) acc[j] += hp[j];
    }
    #pragma unroll
    for (int j = 0; j < NC; j++) atomicAdd(&red[j], acc[j]);
    __syncthreads();
    int cnt = hi - lo;
    if (cnt < 1) cnt = 1;
    if (t < NC) out[g * NC + t] = red[t] / (float)cnt;
}

// -------- launcher --------
// Order puts gemm1 at launch idx 3 (the ncu-profiled slot) — it is
// CSR-independent, so this is dependency-legal.
extern "C" void kernel_launch(void* const* d_in, const int* in_sizes, int n_in,
                              void* d_out, int out_size) {
    const float* x   = (const float*)d_in[0];
    const int*   ei  = (const int*)d_in[1];
    const int*   bat = (const int*)d_in[2];
    const float* W1  = (const float*)d_in[3];
    const float* as1 = (const float*)d_in[4];
    const float* ad1 = (const float*)d_in[5];
    const float* b1  = (const float*)d_in[6];
    const float* W2  = (const float*)d_in[7];
    const float* as2 = (const float*)d_in[8];
    const float* ad2 = (const float*)d_in[9];
    const float* b2  = (const float*)d_in[10];
    float* out = (float*)d_out;

    init_counts_kernel<<<(NN + 255) / 256, 256>>>();
    count_kernel<<<(EE / 4 + 255) / 256, 256>>>(ei);
    scan_kernel<<<1, 1024>>>();
    gemm1_kernel<<<dim3(D1 / 64, (NN + 63) / 64), 256>>>(x, W1, as1, ad1);
    scatter_kernel<<<(EE / 4 + 255) / 256, 256>>>(ei);

    agg1_kernel<<<NN, 128>>>(b1);

    node2_kernel<<<(NN + 7) / 8, 256>>>(W2, as2, ad2);
    agg2_kernel<<<(NN + 7) / 8, 256>>>(b2);
    pool_kernel<<<NG, 256>>>(bat, out);
}

// round 7
// speedup vs baseline: 1.8714x; 1.8714x over previous
#include <cuda_runtime.h>
#include <cuda_fp16.h>
#include <math.h>
#include <stdint.h>

#define NN 20000
#define EE 320000
#define ET 340000      // EE + NN self loops
#define FIN 128
#define D1 512         // HEADS*HID
#define HEADS 8
#define HID 64
#define NC 10
#define NG 64

// -------- scratch (device globals; no allocations allowed) --------
__device__ float  g_h1[(size_t)NN * D1];     // layer1 features fp32 (gathered by agg1)
__device__ float  g_h1act[(size_t)NN * D1];  // elu(agg1 + b1)
__device__ __half g_xh[(size_t)NN * FIN];    // x in fp16
__device__ __half g_w1h[FIN * D1];           // W1 in fp16
__device__ float  g_asrc1[NN * HEADS];
__device__ float  g_adst1[NN * HEADS];
__device__ float  g_h2[NN * NC];
__device__ float  g_asrc2[NN];
__device__ float  g_adst2[NN];
__device__ float  g_agg2[NN * NC];
__device__ int    g_counts[NN];
__device__ int    g_rowptr[NN + 1];
__device__ int    g_wptr[NN];
__device__ int    g_csrc[ET];

__device__ __forceinline__ float wredsum(float v) {
    #pragma unroll
    for (int o = 16; o; o >>= 1) v += __shfl_xor_sync(0xffffffffu, v, o);
    return v;
}
__device__ __forceinline__ uint32_t sptr(const void* p) {
    return (uint32_t)__cvta_generic_to_shared(p);
}

// -------- fp16 converts --------
__global__ void xh_kernel(const float* __restrict__ X) {
    int i = blockIdx.x * 256 + threadIdx.x;          // one float4
    if (i >= NN * FIN / 4) return;
    float4 v = ((const float4*)X)[i];
    union { __half2 h[2]; uint2 u; } pk;
    pk.h[0] = __floats2half2_rn(v.x, v.y);
    pk.h[1] = __floats2half2_rn(v.z, v.w);
    ((uint2*)g_xh)[i] = pk.u;
}
__global__ void wh_kernel(const float* __restrict__ W) {
    int i = blockIdx.x * 256 + threadIdx.x;
    if (i >= FIN * D1 / 4) return;
    float4 v = ((const float4*)W)[i];
    union { __half2 h[2]; uint2 u; } pk;
    pk.h[0] = __floats2half2_rn(v.x, v.y);
    pk.h[1] = __floats2half2_rn(v.z, v.w);
    ((uint2*)g_w1h)[i] = pk.u;
}

// -------- CSR build --------
__global__ void init_counts_kernel() {
    int i = blockIdx.x * blockDim.x + threadIdx.x;
    if (i < NN) g_counts[i] = 1;     // self-loop pre-counted
}
__global__ void count_kernel(const int* __restrict__ ei) {
    int i = blockIdx.x * blockDim.x + threadIdx.x;
    if (i >= EE / 4) return;
    int4 d = ((const int4*)(ei + EE))[i];
    atomicAdd(&g_counts[d.x], 1);
    atomicAdd(&g_counts[d.y], 1);
    atomicAdd(&g_counts[d.z], 1);
    atomicAdd(&g_counts[d.w], 1);
}
__global__ void scan_kernel() {
    __shared__ int sh[1024];
    int t = threadIdx.x;
    const int CH = (NN + 1023) / 1024;
    int base = t * CH;
    int s = 0;
    for (int i = 0; i < CH; i++) {
        int idx = base + i;
        if (idx < NN) s += g_counts[idx];
    }
    sh[t] = s;
    __syncthreads();
    for (int off = 1; off < 1024; off <<= 1) {
        int v = (t >= off) ? sh[t - off] : 0;
        __syncthreads();
        sh[t] += v;
        __syncthreads();
    }
    int run = sh[t] - s;
    for (int i = 0; i < CH; i++) {
        int idx = base + i;
        if (idx < NN) {
            g_rowptr[idx] = run;
            g_csrc[run]   = idx;      // self-loop in first slot
            g_wptr[idx]   = run + 1;
            run += g_counts[idx];
        }
    }
    if (t == 1023) g_rowptr[NN] = sh[1023];
}
__global__ void scatter_kernel(const int* __restrict__ ei) {
    int i = blockIdx.x * blockDim.x + threadIdx.x;
    if (i >= EE / 4) return;
    int4 s = ((const int4*)ei)[i];
    int4 d = ((const int4*)(ei + EE))[i];
    int p0 = atomicAdd(&g_wptr[d.x], 1);
    int p1 = atomicAdd(&g_wptr[d.y], 1);
    int p2 = atomicAdd(&g_wptr[d.z], 1);
    int p3 = atomicAdd(&g_wptr[d.w], 1);
    g_csrc[p0] = s.x;
    g_csrc[p1] = s.y;
    g_csrc[p2] = s.z;
    g_csrc[p3] = s.w;
}

// -------- tensor-core GEMM1 + fused attention coefs --------
// C[128,64] per block = Xh[128,128] @ W1h[128, nb*64..]; fp32 accum.
// 8 warps, warp w owns rows [16w,16w+16); 2 K passes of 64.
__global__ void gemm1_tc_kernel(const float* __restrict__ asv,
                                const float* __restrict__ adv) {
    __shared__ __half Xs[128][72];   // pad 8 halfs: 36-word stride, LDSM conflict-free
    __shared__ __half Ws[64][72];
    __shared__ float sa[64], sd[64];
    int t = threadIdx.x, lane = t & 31, wid = t >> 5;
    int nb = blockIdx.x;             // head / 64-col block
    int mb = blockIdx.y;
    int mB = mb * 128;
    if (t < 64) { sa[t] = asv[nb * 64 + t]; sd[t] = adv[nb * 64 + t]; }

    float acc[8][4];
    #pragma unroll
    for (int i = 0; i < 8; i++)
        #pragma unroll
        for (int j = 0; j < 4; j++) acc[i][j] = 0.f;

    #pragma unroll
    for (int pass = 0; pass < 2; pass++) {
        int k0g = pass * 64;
        __syncthreads();
        // Xs tile: 128 rows x 64 halfs, uint4 (8 halfs) chunks
        #pragma unroll
        for (int p = 0; p < 4; p++) {
            int idx = t + p * 256;           // 0..1023
            int row = idx >> 3, ch = idx & 7;
            int grow = mB + row;
            uint4 v = make_uint4(0u, 0u, 0u, 0u);
            if (grow < NN)
                v = *(const uint4*)&g_xh[(size_t)grow * FIN + k0g + ch * 8];
            *(uint4*)&Xs[row][ch * 8] = v;
        }
        // Ws tile: 64 rows x 64 halfs
        #pragma unroll
        for (int p = 0; p < 2; p++) {
            int idx = t + p * 256;           // 0..511
            int row = idx >> 3, ch = idx & 7;
            uint4 v = *(const uint4*)&g_w1h[(size_t)(k0g + row) * D1 + nb * 64 + ch * 8];
            *(uint4*)&Ws[row][ch * 8] = v;
        }
        __syncthreads();

        #pragma unroll
        for (int ks = 0; ks < 4; ks++) {
            int k0 = ks * 16;
            uint32_t a0, a1, a2, a3;
            {
                uint32_t ad = sptr(&Xs[wid * 16 + (lane & 15)][k0 + ((lane & 16) ? 8 : 0)]);
                asm volatile(
                    "ldmatrix.sync.aligned.m8n8.x4.shared.b16 {%0,%1,%2,%3}, [%4];"
                    : "=r"(a0), "=r"(a1), "=r"(a2), "=r"(a3) : "r"(ad));
            }
            #pragma unroll
            for (int ntp = 0; ntp < 4; ntp++) {   // pairs of n8-tiles
                uint32_t b0, b1, b2, b3;
                uint32_t bd = sptr(&Ws[k0 + (lane & 15)][ntp * 16 + ((lane & 16) ? 8 : 0)]);
                asm volatile(
                    "ldmatrix.sync.aligned.m8n8.x4.trans.shared.b16 {%0,%1,%2,%3}, [%4];"
                    : "=r"(b0), "=r"(b1), "=r"(b2), "=r"(b3) : "r"(bd));
                asm volatile(
                    "mma.sync.aligned.m16n8k16.row.col.f32.f16.f16.f32 "
                    "{%0,%1,%2,%3}, {%4,%5,%6,%7}, {%8,%9}, {%0,%1,%2,%3};"
                    : "+f"(acc[2 * ntp][0]), "+f"(acc[2 * ntp][1]),
                      "+f"(acc[2 * ntp][2]), "+f"(acc[2 * ntp][3])
                    : "r"(a0), "r"(a1), "r"(a2), "r"(a3), "r"(b0), "r"(b1));
                asm volatile(
                    "mma.sync.aligned.m16n8k16.row.col.f32.f16.f16.f32 "
                    "{%0,%1,%2,%3}, {%4,%5,%6,%7}, {%8,%9}, {%0,%1,%2,%3};"
                    : "+f"(acc[2 * ntp + 1][0]), "+f"(acc[2 * ntp + 1][1]),
                      "+f"(acc[2 * ntp + 1][2]), "+f"(acc[2 * ntp + 1][3])
                    : "r"(a0), "r"(a1), "r"(a2), "r"(a3), "r"(b2), "r"(b3));
            }
        }
    }

    // epilogue: store h1 fp32 + complete per-head coefs (BN==HID)
    int rlo = mB + wid * 16 + (lane >> 2);
    int rhi = rlo + 8;
    int q = lane & 3;
    float slo = 0.f, shi = 0.f, dlo = 0.f, dhi = 0.f;
    #pragma unroll
    for (int nt = 0; nt < 8; nt++) {
        int c = nt * 8 + 2 * q;
        slo += acc[nt][0] * sa[c] + acc[nt][1] * sa[c + 1];
        dlo += acc[nt][0] * sd[c] + acc[nt][1] * sd[c + 1];
        shi += acc[nt][2] * sa[c] + acc[nt][3] * sa[c + 1];
        dhi += acc[nt][2] * sd[c] + acc[nt][3] * sd[c + 1];
        if (rlo < NN)
            *(float2*)&g_h1[(size_t)rlo * D1 + nb * 64 + c] = make_float2(acc[nt][0], acc[nt][1]);
        if (rhi < NN)
            *(float2*)&g_h1[(size_t)rhi * D1 + nb * 64 + c] = make_float2(acc[nt][2], acc[nt][3]);
    }
    #pragma unroll
    for (int o = 1; o <= 2; o <<= 1) {
        slo += __shfl_xor_sync(0xffffffffu, slo, o);
        dlo += __shfl_xor_sync(0xffffffffu, dlo, o);
        shi += __shfl_xor_sync(0xffffffffu, shi, o);
        dhi += __shfl_xor_sync(0xffffffffu, dhi, o);
    }
    if (q == 0) {
        if (rlo < NN) { g_asrc1[rlo * 8 + nb] = slo; g_adst1[rlo * 8 + nb] = dlo; }
        if (rhi < NN) { g_asrc1[rhi * 8 + nb] = shi; g_adst1[rhi * 8 + nb] = dhi; }
    }
}

// -------- layer-1 edge softmax + aggregation (R2-measured version) --------
__global__ void agg1_kernel(const float* __restrict__ b1) {
    int d = blockIdx.x;
    int t = threadIdx.x;   // 128
    __shared__ float sadst[8], salpha[128], sinv[8];
    __shared__ int ssrc[16];
    int beg = g_rowptr[d];
    int deg = g_rowptr[d + 1] - beg;
    if (t < 8) sadst[t] = g_adst1[d * 8 + t];
    int h4 = t >> 4;
    float4 acc = make_float4(0.f, 0.f, 0.f, 0.f);
    float wpart = 0.f;

    for (int base = 0; base < deg; base += 16) {
        int cn = min(16, deg - base);
        __syncthreads();
        if (t < cn) ssrc[t] = g_csrc[beg + base + t];
        if (t < cn * 8) {
            int i = t >> 3, h = t & 7;
            float e = g_asrc1[g_csrc[beg + base + i] * 8 + h] + sadst[h];
            e = e > 0.f ? e : 0.2f * e;
            float w = __expf(e);
            salpha[t] = w;
            wpart += w;
        }
        __syncthreads();
        #pragma unroll 4
        for (int i = 0; i < cn; i++) {
            float a = salpha[i * 8 + h4];
            const float4 hv = *(const float4*)&g_h1[(size_t)ssrc[i] * D1 + 4 * t];
            acc.x += a * hv.x; acc.y += a * hv.y;
            acc.z += a * hv.z; acc.w += a * hv.w;
        }
    }
    __syncthreads();
    salpha[t] = wpart;
    __syncthreads();
    if (t < 8) {
        float s = 0.f;
        #pragma unroll
        for (int j = 0; j < 16; j++) s += salpha[t + 8 * j];
        sinv[t] = 1.f / (s + 1e-16f);
    }
    __syncthreads();
    float inv = sinv[h4];
    float4 bv = *(const float4*)&b1[4 * t];
    float4 o;
    o.x = acc.x * inv + bv.x; o.x = o.x > 0.f ? o.x : expm1f(o.x);
    o.y = acc.y * inv + bv.y; o.y = o.y > 0.f ? o.y : expm1f(o.y);
    o.z = acc.z * inv + bv.z; o.z = o.z > 0.f ? o.z : expm1f(o.z);
    o.w = acc.w * inv + bv.w; o.w = o.w > 0.f ? o.w : expm1f(o.w);
    *(float4*)&g_h1act[(size_t)d * D1 + 4 * t] = o;
}

// -------- layer 2 GEMV + coefficients (warp per node, transposed W2 smem) --------
__global__ void node2_kernel(const float* __restrict__ W2,
                             const float* __restrict__ as2,
                             const float* __restrict__ ad2) {
    __shared__ float Ws[NC * D1];   // [j][c] transposed
    __shared__ float sas[NC], sad[NC];
    int t = threadIdx.x;
    for (int i = t; i < D1 * NC; i += 256) {
        int c = i / NC, j = i - c * NC;
        Ws[j * D1 + c] = W2[i];
    }
    if (t < NC) { sas[t] = as2[t]; sad[t] = ad2[t]; }
    __syncthreads();
    int n = blockIdx.x * 8 + (t >> 5);
    if (n >= NN) return;
    int lane = t & 31;
    const float* hp = &g_h1act[(size_t)n * D1];
    float acc[NC];
    #pragma unroll
    for (int j = 0; j < NC; j++) acc[j] = 0.f;
    for (int c = lane; c < D1; c += 32) {
        float xv = hp[c];
        #pragma unroll
        for (int j = 0; j < NC; j++) acc[j] += xv * Ws[j * D1 + c];
    }
    #pragma unroll
    for (int j = 0; j < NC; j++) acc[j] = wredsum(acc[j]);
    if (lane == 0) {
        float s = 0.f, dd = 0.f;
        #pragma unroll
        for (int j = 0; j < NC; j++) {
            g_h2[n * NC + j] = acc[j];
            s  += acc[j] * sas[j];
            dd += acc[j] * sad[j];
        }
        g_asrc2[n] = s;
        g_adst2[n] = dd;
    }
}

// -------- layer-2 edge softmax + aggregation (warp per dst, single pass) --------
__global__ void agg2_kernel(const float* __restrict__ b2) {
    int n = blockIdx.x * 8 + (threadIdx.x >> 5);
    if (n >= NN) return;
    int lane = threadIdx.x & 31;
    int beg = g_rowptr[n], end = g_rowptr[n + 1];
    float adv = g_adst2[n];
    float s = 0.f;
    float acc[NC];
    #pragma unroll
    for (int j = 0; j < NC; j++) acc[j] = 0.f;
    for (int i = beg + lane; i < end; i += 32) {
        int sn = g_csrc[i];
        float e = g_asrc2[sn] + adv;
        e = e > 0.f ? e : 0.2f * e;
        float w = __expf(e);
        s += w;
        const float* hp = &g_h2[sn * NC];
        #pragma unroll
        for (int j = 0; j < NC; j++) acc[j] += w * hp[j];
    }
    s = wredsum(s);
    #pragma unroll
    for (int j = 0; j < NC; j++) acc[j] = wredsum(acc[j]);
    if (lane == 0) {
        float inv = 1.f / (s + 1e-16f);
        #pragma unroll
        for (int j = 0; j < NC; j++)
            g_agg2[n * NC + j] = acc[j] * inv + b2[j];
    }
}

// -------- mean pooling per graph (batch is sorted) --------
__global__ void pool_kernel(const int* __restrict__ batch,
                            float* __restrict__ out) {
    int g = blockIdx.x;
    int t = threadIdx.x;
    int lo, hi;
    { int a = 0, b = NN;
      while (a < b) { int mid = (a + b) >> 1; if (batch[mid] < g) a = mid + 1; else b = mid; }
      lo = a; }
    { int a = lo, b = NN;
      while (a < b) { int mid = (a + b) >> 1; if (batch[mid] < g + 1) a = mid + 1; else b = mid; }
      hi = a; }
    __shared__ float red[NC];
    if (t < NC) red[t] = 0.f;
    __syncthreads();
    float acc[NC];
    #pragma unroll
    for (int j = 0; j < NC; j++) acc[j] = 0.f;
    for (int i = lo + t; i < hi; i += 256) {
        const float* hp = &g_agg2[i * NC];
        #pragma unroll
        for (int j = 0; j < NC; j++) acc[j] += hp[j];
    }
    #pragma unroll
    for (int j = 0; j < NC; j++) atomicAdd(&red[j], acc[j]);
    __syncthreads();
    int cnt = hi - lo;
    if (cnt < 1) cnt = 1;
    if (t < NC) out[g * NC + t] = red[t] / (float)cnt;
}

// -------- launcher (gemm1_tc at launch idx 3 for profiling) --------
extern "C" void kernel_launch(void* const* d_in, const int* in_sizes, int n_in,
                              void* d_out, int out_size) {
    const float* x   = (const float*)d_in[0];
    const int*   ei  = (const int*)d_in[1];
    const int*   bat = (const int*)d_in[2];
    const float* W1  = (const float*)d_in[3];
    const float* as1 = (const float*)d_in[4];
    const float* ad1 = (const float*)d_in[5];
    const float* b1  = (const float*)d_in[6];
    const float* W2  = (const float*)d_in[7];
    const float* as2 = (const float*)d_in[8];
    const float* ad2 = (const float*)d_in[9];
    const float* b2  = (const float*)d_in[10];
    float* out = (float*)d_out;

    xh_kernel<<<(NN * FIN / 4 + 255) / 256, 256>>>(x);
    wh_kernel<<<(FIN * D1 / 4 + 255) / 256, 256>>>(W1);
    init_counts_kernel<<<(NN + 255) / 256, 256>>>();
    gemm1_tc_kernel<<<dim3(HEADS, (NN + 127) / 128), 256>>>(as1, ad1);
    count_kernel<<<(EE / 4 + 255) / 256, 256>>>(ei);
    scan_kernel<<<1, 1024>>>();
    scatter_kernel<<<(EE / 4 + 255) / 256, 256>>>(ei);

    agg1_kernel<<<NN, 128>>>(b1);

    node2_kernel<<<(NN + 7) / 8, 256>>>(W2, as2, ad2);
    agg2_kernel<<<(NN + 7) / 8, 256>>>(b2);
    pool_kernel<<<NG, 256>>>(bat, out);
}

// round 8
// speedup vs baseline: 1.9187x; 1.0253x over previous
#include <cuda_runtime.h>
#include <cuda_fp16.h>
#include <math.h>
#include <stdint.h>

#define NN 20000
#define EE 320000
#define ET 340000      // EE + NN self loops
#define FIN 128
#define D1 512         // HEADS*HID
#define HEADS 8
#define HID 64
#define NC 10
#define NG 64

// -------- scratch (device globals; no allocations allowed) --------
__device__ __half g_h1h[(size_t)NN * D1];    // layer1 features fp16 (gathered by agg1)
__device__ float  g_h1act[(size_t)NN * D1];  // elu(agg1 + b1)
__device__ __half g_xh[(size_t)NN * FIN];    // x in fp16
__device__ __half g_w1h[FIN * D1];           // W1 in fp16
__device__ float  g_asrc1[NN * HEADS];
__device__ float  g_adst1[NN * HEADS];
__device__ float  g_h2[NN * NC];
__device__ float  g_asrc2[NN];
__device__ float  g_adst2[NN];
__device__ float  g_agg2[NN * NC];
__device__ int    g_counts[NN];
__device__ int    g_rowptr[NN + 1];
__device__ int    g_wptr[NN];
__device__ int    g_csrc[ET];

struct alignas(8) H4 { __half2 a, b; };   // 4 halfs, one LDG.64

__device__ __forceinline__ float wredsum(float v) {
    #pragma unroll
    for (int o = 16; o; o >>= 1) v += __shfl_xor_sync(0xffffffffu, v, o);
    return v;
}
__device__ __forceinline__ uint32_t sptr(const void* p) {
    return (uint32_t)__cvta_generic_to_shared(p);
}

// -------- fp16 converts --------
__global__ void xh_kernel(const float* __restrict__ X) {
    int i = blockIdx.x * 256 + threadIdx.x;          // one float4
    if (i >= NN * FIN / 4) return;
    float4 v = ((const float4*)X)[i];
    H4 pk;
    pk.a = __floats2half2_rn(v.x, v.y);
    pk.b = __floats2half2_rn(v.z, v.w);
    ((H4*)g_xh)[i] = pk;
}
__global__ void wh_kernel(const float* __restrict__ W) {
    int i = blockIdx.x * 256 + threadIdx.x;
    if (i >= FIN * D1 / 4) return;
    float4 v = ((const float4*)W)[i];
    H4 pk;
    pk.a = __floats2half2_rn(v.x, v.y);
    pk.b = __floats2half2_rn(v.z, v.w);
    ((H4*)g_w1h)[i] = pk;
}

// -------- CSR build --------
__global__ void init_counts_kernel() {
    int i = blockIdx.x * blockDim.x + threadIdx.x;
    if (i < NN) g_counts[i] = 1;     // self-loop pre-counted
}
__global__ void count_kernel(const int* __restrict__ ei) {
    int i = blockIdx.x * blockDim.x + threadIdx.x;
    if (i >= EE / 4) return;
    int4 d = ((const int4*)(ei + EE))[i];
    atomicAdd(&g_counts[d.x], 1);
    atomicAdd(&g_counts[d.y], 1);
    atomicAdd(&g_counts[d.z], 1);
    atomicAdd(&g_counts[d.w], 1);
}
__global__ void scan_kernel() {
    __shared__ int sh[1024];
    int t = threadIdx.x;
    const int CH = (NN + 1023) / 1024;
    int base = t * CH;
    int s = 0;
    for (int i = 0; i < CH; i++) {
        int idx = base + i;
        if (idx < NN) s += g_counts[idx];
    }
    sh[t] = s;
    __syncthreads();
    for (int off = 1; off < 1024; off <<= 1) {
        int v = (t >= off) ? sh[t - off] : 0;
        __syncthreads();
        sh[t] += v;
        __syncthreads();
    }
    int run = sh[t] - s;
    for (int i = 0; i < CH; i++) {
        int idx = base + i;
        if (idx < NN) {
            g_rowptr[idx] = run;
            g_csrc[run]   = idx;      // self-loop in first slot
            g_wptr[idx]   = run + 1;
            run += g_counts[idx];
        }
    }
    if (t == 1023) g_rowptr[NN] = sh[1023];
}
__global__ void scatter_kernel(const int* __restrict__ ei) {
    int i = blockIdx.x * blockDim.x + threadIdx.x;
    if (i >= EE / 4) return;
    int4 s = ((const int4*)ei)[i];
    int4 d = ((const int4*)(ei + EE))[i];
    int p0 = atomicAdd(&g_wptr[d.x], 1);
    int p1 = atomicAdd(&g_wptr[d.y], 1);
    int p2 = atomicAdd(&g_wptr[d.z], 1);
    int p3 = atomicAdd(&g_wptr[d.w], 1);
    g_csrc[p0] = s.x;
    g_csrc[p1] = s.y;
    g_csrc[p2] = s.z;
    g_csrc[p3] = s.w;
}

// -------- tensor-core GEMM1 + fused attention coefs --------
__global__ void gemm1_tc_kernel(const float* __restrict__ asv,
                                const float* __restrict__ adv) {
    __shared__ __half Xs[128][72];   // pad 8 halfs: LDSM conflict-free
    __shared__ __half Ws[64][72];
    __shared__ float sa[64], sd[64];
    int t = threadIdx.x, lane = t & 31, wid = t >> 5;
    int nb = blockIdx.x;             // head / 64-col block
    int mb = blockIdx.y;
    int mB = mb * 128;
    if (t < 64) { sa[t] = asv[nb * 64 + t]; sd[t] = adv[nb * 64 + t]; }

    float acc[8][4];
    #pragma unroll
    for (int i = 0; i < 8; i++)
        #pragma unroll
        for (int j = 0; j < 4; j++) acc[i][j] = 0.f;

    #pragma unroll
    for (int pass = 0; pass < 2; pass++) {
        int k0g = pass * 64;
        __syncthreads();
        #pragma unroll
        for (int p = 0; p < 4; p++) {
            int idx = t + p * 256;           // 0..1023
            int row = idx >> 3, ch = idx & 7;
            int grow = mB + row;
            uint4 v = make_uint4(0u, 0u, 0u, 0u);
            if (grow < NN)
                v = *(const uint4*)&g_xh[(size_t)grow * FIN + k0g + ch * 8];
            *(uint4*)&Xs[row][ch * 8] = v;
        }
        #pragma unroll
        for (int p = 0; p < 2; p++) {
            int idx = t + p * 256;           // 0..511
            int row = idx >> 3, ch = idx & 7;
            uint4 v = *(const uint4*)&g_w1h[(size_t)(k0g + row) * D1 + nb * 64 + ch * 8];
            *(uint4*)&Ws[row][ch * 8] = v;
        }
        __syncthreads();

        #pragma unroll
        for (int ks = 0; ks < 4; ks++) {
            int k0 = ks * 16;
            uint32_t a0, a1, a2, a3;
            {
                uint32_t ad = sptr(&Xs[wid * 16 + (lane & 15)][k0 + ((lane & 16) ? 8 : 0)]);
                asm volatile(
                    "ldmatrix.sync.aligned.m8n8.x4.shared.b16 {%0,%1,%2,%3}, [%4];"
                    : "=r"(a0), "=r"(a1), "=r"(a2), "=r"(a3) : "r"(ad));
            }
            #pragma unroll
            for (int ntp = 0; ntp < 4; ntp++) {   // pairs of n8-tiles
                uint32_t b0, b1, b2, b3;
                uint32_t bd = sptr(&Ws[k0 + (lane & 15)][ntp * 16 + ((lane & 16) ? 8 : 0)]);
                asm volatile(
                    "ldmatrix.sync.aligned.m8n8.x4.trans.shared.b16 {%0,%1,%2,%3}, [%4];"
                    : "=r"(b0), "=r"(b1), "=r"(b2), "=r"(b3) : "r"(bd));
                asm volatile(
                    "mma.sync.aligned.m16n8k16.row.col.f32.f16.f16.f32 "
                    "{%0,%1,%2,%3}, {%4,%5,%6,%7}, {%8,%9}, {%0,%1,%2,%3};"
                    : "+f"(acc[2 * ntp][0]), "+f"(acc[2 * ntp][1]),
                      "+f"(acc[2 * ntp][2]), "+f"(acc[2 * ntp][3])
                    : "r"(a0), "r"(a1), "r"(a2), "r"(a3), "r"(b0), "r"(b1));
                asm volatile(
                    "mma.sync.aligned.m16n8k16.row.col.f32.f16.f16.f32 "
                    "{%0,%1,%2,%3}, {%4,%5,%6,%7}, {%8,%9}, {%0,%1,%2,%3};"
                    : "+f"(acc[2 * ntp + 1][0]), "+f"(acc[2 * ntp + 1][1]),
                      "+f"(acc[2 * ntp + 1][2]), "+f"(acc[2 * ntp + 1][3])
                    : "r"(a0), "r"(a1), "r"(a2), "r"(a3), "r"(b2), "r"(b3));
            }
        }
    }

    // epilogue: store h1 fp16 + complete per-head coefs (BN==HID)
    int rlo = mB + wid * 16 + (lane >> 2);
    int rhi = rlo + 8;
    int q = lane & 3;
    float slo = 0.f, shi = 0.f, dlo = 0.f, dhi = 0.f;
    #pragma unroll
    for (int nt = 0; nt < 8; nt++) {
        int c = nt * 8 + 2 * q;
        slo += acc[nt][0] * sa[c] + acc[nt][1] * sa[c + 1];
        dlo += acc[nt][0] * sd[c] + acc[nt][1] * sd[c + 1];
        shi += acc[nt][2] * sa[c] + acc[nt][3] * sa[c + 1];
        dhi += acc[nt][2] * sd[c] + acc[nt][3] * sd[c + 1];
        if (rlo < NN)
            *(__half2*)&g_h1h[(size_t)rlo * D1 + nb * 64 + c] =
                __floats2half2_rn(acc[nt][0], acc[nt][1]);
        if (rhi < NN)
            *(__half2*)&g_h1h[(size_t)rhi * D1 + nb * 64 + c] =
                __floats2half2_rn(acc[nt][2], acc[nt][3]);
    }
    #pragma unroll
    for (int o = 1; o <= 2; o <<= 1) {
        slo += __shfl_xor_sync(0xffffffffu, slo, o);
        dlo += __shfl_xor_sync(0xffffffffu, dlo, o);
        shi += __shfl_xor_sync(0xffffffffu, shi, o);
        dhi += __shfl_xor_sync(0xffffffffu, dhi, o);
    }
    if (q == 0) {
        if (rlo < NN) { g_asrc1[rlo * 8 + nb] = slo; g_adst1[rlo * 8 + nb] = dlo; }
        if (rhi < NN) { g_asrc1[rhi * 8 + nb] = shi; g_adst1[rhi * 8 + nb] = dhi; }
    }
}

// -------- layer-1 edge softmax + aggregation: one block / dst node --------
__global__ void agg1_kernel(const float* __restrict__ b1) {
    int d = blockIdx.x;
    int t = threadIdx.x;   // 128
    __shared__ float sadst[8], salpha[128], sinv[8];
    __shared__ int ssrc[16];
    int beg = g_rowptr[d];
    int deg = g_rowptr[d + 1] - beg;
    if (t < 8) sadst[t] = g_adst1[d * 8 + t];
    int h4 = t >> 4;
    float4 acc = make_float4(0.f, 0.f, 0.f, 0.f);
    float wpart = 0.f;

    for (int base = 0; base < deg; base += 16) {
        int cn = min(16, deg - base);
        __syncthreads();
        if (t < cn) ssrc[t] = g_csrc[beg + base + t];
        if (t < cn * 8) {
            int i = t >> 3, h = t & 7;
            float e = g_asrc1[g_csrc[beg + base + i] * 8 + h] + sadst[h];
            e = e > 0.f ? e : 0.2f * e;
            float w = __expf(e);
            salpha[t] = w;
            wpart += w;
        }
        __syncthreads();
        #pragma unroll 4
        for (int i = 0; i < cn; i++) {
            float a = salpha[i * 8 + h4];
            H4 v = *(const H4*)&g_h1h[(size_t)ssrc[i] * D1 + 4 * t];
            float2 f0 = __half22float2(v.a);
            float2 f1 = __half22float2(v.b);
            acc.x += a * f0.x; acc.y += a * f0.y;
            acc.z += a * f1.x; acc.w += a * f1.y;
        }
    }
    __syncthreads();
    salpha[t] = wpart;
    __syncthreads();
    if (t < 8) {
        float s = 0.f;
        #pragma unroll
        for (int j = 0; j < 16; j++) s += salpha[t + 8 * j];
        sinv[t] = 1.f / (s + 1e-16f);
    }
    __syncthreads();
    float inv = sinv[h4];
    float4 bv = *(const float4*)&b1[4 * t];
    float4 o;
    o.x = acc.x * inv + bv.x; o.x = o.x > 0.f ? o.x : expm1f(o.x);
    o.y = acc.y * inv + bv.y; o.y = o.y > 0.f ? o.y : expm1f(o.y);
    o.z = acc.z * inv + bv.z; o.z = o.z > 0.f ? o.z : expm1f(o.z);
    o.w = acc.w * inv + bv.w; o.w = o.w > 0.f ? o.w : expm1f(o.w);
    *(float4*)&g_h1act[(size_t)d * D1 + 4 * t] = o;
}

// -------- layer 2 GEMV + coefficients (warp per node, transposed W2 smem) --------
__global__ void node2_kernel(const float* __restrict__ W2,
                             const float* __restrict__ as2,
                             const float* __restrict__ ad2) {
    __shared__ float Ws[NC * D1];   // [j][c] transposed
    __shared__ float sas[NC], sad[NC];
    int t = threadIdx.x;
    for (int i = t; i < D1 * NC; i += 256) {
        int c = i / NC, j = i - c * NC;
        Ws[j * D1 + c] = W2[i];
    }
    if (t < NC) { sas[t] = as2[t]; sad[t] = ad2[t]; }
    __syncthreads();
    int n = blockIdx.x * 8 + (t >> 5);
    if (n >= NN) return;
    int lane = t & 31;
    const float* hp = &g_h1act[(size_t)n * D1];
    float acc[NC];
    #pragma unroll
    for (int j = 0; j < NC; j++) acc[j] = 0.f;
    for (int c = lane; c < D1; c += 32) {
        float xv = hp[c];
        #pragma unroll
        for (int j = 0; j < NC; j++) acc[j] += xv * Ws[j * D1 + c];
    }
    #pragma unroll
    for (int j = 0; j < NC; j++) acc[j] = wredsum(acc[j]);
    if (lane == 0) {
        float s = 0.f, dd = 0.f;
        #pragma unroll
        for (int j = 0; j < NC; j++) {
            g_h2[n * NC + j] = acc[j];
            s  += acc[j] * sas[j];
            dd += acc[j] * sad[j];
        }
        g_asrc2[n] = s;
        g_adst2[n] = dd;
    }
}

// -------- layer-2 edge softmax + aggregation (warp per dst, single pass) --------
__global__ void agg2_kernel(const float* __restrict__ b2) {
    int n = blockIdx.x * 8 + (threadIdx.x >> 5);
    if (n >= NN) return;
    int lane = threadIdx.x & 31;
    int beg = g_rowptr[n], end = g_rowptr[n + 1];
    float adv = g_adst2[n];
    float s = 0.f;
    float acc[NC];
    #pragma unroll
    for (int j = 0; j < NC; j++) acc[j] = 0.f;
    for (int i = beg + lane; i < end; i += 32) {
        int sn = g_csrc[i];
        float e = g_asrc2[sn] + adv;
        e = e > 0.f ? e : 0.2f * e;
        float w = __expf(e);
        s += w;
        const float* hp = &g_h2[sn * NC];
        #pragma unroll
        for (int j = 0; j < NC; j++) acc[j] += w * hp[j];
    }
    s = wredsum(s);
    #pragma unroll
    for (int j = 0; j < NC; j++) acc[j] = wredsum(acc[j]);
    if (lane == 0) {
        float inv = 1.f / (s + 1e-16f);
        #pragma unroll
        for (int j = 0; j < NC; j++)
            g_agg2[n * NC + j] = acc[j] * inv + b2[j];
    }
}

// -------- mean pooling per graph (batch is sorted) --------
__global__ void pool_kernel(const int* __restrict__ batch,
                            float* __restrict__ out) {
    int g = blockIdx.x;
    int t = threadIdx.x;
    int lo, hi;
    { int a = 0, b = NN;
      while (a < b) { int mid = (a + b) >> 1; if (batch[mid] < g) a = mid + 1; else b = mid; }
      lo = a; }
    { int a = lo, b = NN;
      while (a < b) { int mid = (a + b) >> 1; if (batch[mid] < g + 1) a = mid + 1; else b = mid; }
      hi = a; }
    __shared__ float red[NC];
    if (t < NC) red[t] = 0.f;
    __syncthreads();
    float acc[NC];
    #pragma unroll
    for (int j = 0; j < NC; j++) acc[j] = 0.f;
    for (int i = lo + t; i < hi; i += 256) {
        const float* hp = &g_agg2[i * NC];
        #pragma unroll
        for (int j = 0; j < NC; j++) acc[j] += hp[j];
    }
    #pragma unroll
    for (int j = 0; j < NC; j++) atomicAdd(&red[j], acc[j]);
    __syncthreads();
    int cnt = hi - lo;
    if (cnt < 1) cnt = 1;
    if (t < NC) out[g * NC + t] = red[t] / (float)cnt;
}

// -------- launcher --------
extern "C" void kernel_launch(void* const* d_in, const int* in_sizes, int n_in,
                              void* d_out, int out_size) {
    const float* x   = (const float*)d_in[0];
    const int*   ei  = (const int*)d_in[1];
    const int*   bat = (const int*)d_in[2];
    const float* W1  = (const float*)d_in[3];
    const float* as1 = (const float*)d_in[4];
    const float* ad1 = (const float*)d_in[5];
    const float* b1  = (const float*)d_in[6];
    const float* W2  = (const float*)d_in[7];
    const float* as2 = (const float*)d_in[8];
    const float* ad2 = (const float*)d_in[9];
    const float* b2  = (const float*)d_in[10];
    float* out = (float*)d_out;

    xh_kernel<<<(NN * FIN / 4 + 255) / 256, 256>>>(x);
    wh_kernel<<<(FIN * D1 / 4 + 255) / 256, 256>>>(W1);
    init_counts_kernel<<<(NN + 255) / 256, 256>>>();
    gemm1_tc_kernel<<<dim3(HEADS, (NN + 127) / 128), 256>>>(as1, ad1);
    count_kernel<<<(EE / 4 + 255) / 256, 256>>>(ei);
    scan_kernel<<<1, 1024>>>();
    scatter_kernel<<<(EE / 4 + 255) / 256, 256>>>(ei);

    agg1_kernel<<<NN, 128>>>(b1);

    node2_kernel<<<(NN + 7) / 8, 256>>>(W2, as2, ad2);
    agg2_kernel<<<(NN + 7) / 8, 256>>>(b2);
    pool_kernel<<<NG, 256>>>(bat, out);
}

// round 9
// speedup vs baseline: 2.0971x; 1.0930x over previous
#include <cuda_runtime.h>
#include <cuda_fp16.h>
#include <math.h>
#include <stdint.h>

#define NN 20000
#define EE 320000
#define ET 340000      // EE + NN self loops
#define FIN 128
#define D1 512         // HEADS*HID
#define HEADS 8
#define HID 64
#define NC 10
#define NG 64
#define NB ((NN + 255) / 256)   // 79 scan blocks

// -------- scratch (device globals; no allocations allowed) --------
__device__ __half g_h1h[(size_t)NN * D1];    // layer1 features fp16 (gathered by agg1)
__device__ float  g_h1act[(size_t)NN * D1];  // elu(agg1 + b1)
__device__ __half g_xh[(size_t)NN * FIN];    // x in fp16
__device__ __half g_w1h[FIN * D1];           // W1 in fp16
__device__ float  g_asrc1[NN * HEADS];
__device__ float  g_adst1[NN * HEADS];
__device__ float  g_ew[(size_t)ET * HEADS];  // per-(edge,head) softmax weights
__device__ float  g_h2[NN * NC];
__device__ float  g_asrc2[NN];
__device__ float  g_adst2[NN];
__device__ float  g_agg2[NN * NC];
__device__ int    g_counts[NN];
__device__ int    g_rowptr[NN + 1];
__device__ int    g_wptr[NN];
__device__ int    g_csrc[ET];
__device__ int    g_edst[ET];
__device__ int    g_bsum[NB];
__device__ int    g_boff[NB];

struct alignas(8) H4 { __half2 a, b; };   // 4 halfs, one LDG.64

__device__ __forceinline__ float wredsum(float v) {
    #pragma unroll
    for (int o = 16; o; o >>= 1) v += __shfl_xor_sync(0xffffffffu, v, o);
    return v;
}
__device__ __forceinline__ uint32_t sptr(const void* p) {
    return (uint32_t)__cvta_generic_to_shared(p);
}

// -------- fp16 converts --------
__global__ void xh_kernel(const float* __restrict__ X) {
    int i = blockIdx.x * 256 + threadIdx.x;          // one float4
    if (i >= NN * FIN / 4) return;
    float4 v = ((const float4*)X)[i];
    H4 pk;
    pk.a = __floats2half2_rn(v.x, v.y);
    pk.b = __floats2half2_rn(v.z, v.w);
    ((H4*)g_xh)[i] = pk;
}
__global__ void wh_kernel(const float* __restrict__ W) {
    int i = blockIdx.x * 256 + threadIdx.x;
    if (i >= FIN * D1 / 4) return;
    float4 v = ((const float4*)W)[i];
    H4 pk;
    pk.a = __floats2half2_rn(v.x, v.y);
    pk.b = __floats2half2_rn(v.z, v.w);
    ((H4*)g_w1h)[i] = pk;
}

// -------- CSR build --------
__global__ void init_counts_kernel() {
    int i = blockIdx.x * blockDim.x + threadIdx.x;
    if (i < NN) g_counts[i] = 1;     // self-loop pre-counted
}
__global__ void count_kernel(const int* __restrict__ ei) {
    int i = blockIdx.x * blockDim.x + threadIdx.x;
    if (i >= EE / 4) return;
    int4 d = ((const int4*)(ei + EE))[i];
    atomicAdd(&g_counts[d.x], 1);
    atomicAdd(&g_counts[d.y], 1);
    atomicAdd(&g_counts[d.z], 1);
    atomicAdd(&g_counts[d.w], 1);
}
// parallel scan, phase A: per-256-node block exclusive scan + block sum
__global__ void scanA_kernel() {
    __shared__ int sh[256];
    int t = threadIdx.x;
    int n = blockIdx.x * 256 + t;
    int c = (n < NN) ? g_counts[n] : 0;
    sh[t] = c;
    __syncthreads();
    #pragma unroll
    for (int off = 1; off < 256; off <<= 1) {
        int v = (t >= off) ? sh[t - off] : 0;
        __syncthreads();
        sh[t] += v;
        __syncthreads();
    }
    if (n < NN) g_rowptr[n] = sh[t] - c;   // block-local exclusive prefix
    if (t == 255) g_bsum[blockIdx.x] = sh[255];
}
// phase B: single block scans the 79 block sums
__global__ void scanB_kernel() {
    __shared__ int sh[128];
    int t = threadIdx.x;
    int v = (t < NB) ? g_bsum[t] : 0;
    sh[t] = v;
    __syncthreads();
    #pragma unroll
    for (int off = 1; off < 128; off <<= 1) {
        int u = (t >= off) ? sh[t - off] : 0;
        __syncthreads();
        sh[t] += u;
        __syncthreads();
    }
    if (t < NB) g_boff[t] = sh[t] - v;     // exclusive
}
// phase C: globalize rowptr, seed self-loop slot, init wptr
__global__ void scanC_kernel() {
    int n = blockIdx.x * blockDim.x + threadIdx.x;
    if (n >= NN) return;
    int r = g_rowptr[n] + g_boff[n >> 8];
    g_rowptr[n] = r;
    g_wptr[n] = r + 1;
    g_csrc[r] = n;
    g_edst[r] = n;
    if (n == 0) g_rowptr[NN] = ET;
}
__global__ void scatter_kernel(const int* __restrict__ ei) {
    int i = blockIdx.x * blockDim.x + threadIdx.x;
    if (i >= EE / 4) return;
    int4 s = ((const int4*)ei)[i];
    int4 d = ((const int4*)(ei + EE))[i];
    int p0 = atomicAdd(&g_wptr[d.x], 1);
    int p1 = atomicAdd(&g_wptr[d.y], 1);
    int p2 = atomicAdd(&g_wptr[d.z], 1);
    int p3 = atomicAdd(&g_wptr[d.w], 1);
    g_csrc[p0] = s.x;  g_edst[p0] = d.x;
    g_csrc[p1] = s.y;  g_edst[p1] = d.y;
    g_csrc[p2] = s.z;  g_edst[p2] = d.z;
    g_csrc[p3] = s.w;  g_edst[p3] = d.w;
}

// -------- edge softmax weights: w[e][h] = exp(leakyrelu(asrc[src][h]+adst[dst][h])) --------
__global__ void ew_kernel() {
    int idx = blockIdx.x * 256 + threadIdx.x;   // e*8+h
    if (idx >= ET * HEADS) return;
    int e = idx >> 3, h = idx & 7;
    int src = g_csrc[e], dst = g_edst[e];
    float v = g_asrc1[src * 8 + h] + g_adst1[dst * 8 + h];
    v = v > 0.f ? v : 0.2f * v;
    g_ew[idx] = __expf(v);
}

// -------- tensor-core GEMM1 + fused attention coefs --------
__global__ void gemm1_tc_kernel(const float* __restrict__ asv,
                                const float* __restrict__ adv) {
    __shared__ __half Xs[128][72];   // pad 8 halfs: LDSM conflict-free
    __shared__ __half Ws[64][72];
    __shared__ float sa[64], sd[64];
    int t = threadIdx.x, lane = t & 31, wid = t >> 5;
    int nb = blockIdx.x;             // head / 64-col block
    int mb = blockIdx.y;
    int mB = mb * 128;
    if (t < 64) { sa[t] = asv[nb * 64 + t]; sd[t] = adv[nb * 64 + t]; }

    float acc[8][4];
    #pragma unroll
    for (int i = 0; i < 8; i++)
        #pragma unroll
        for (int j = 0; j < 4; j++) acc[i][j] = 0.f;

    #pragma unroll
    for (int pass = 0; pass < 2; pass++) {
        int k0g = pass * 64;
        __syncthreads();
        #pragma unroll
        for (int p = 0; p < 4; p++) {
            int idx = t + p * 256;           // 0..1023
            int row = idx >> 3, ch = idx & 7;
            int grow = mB + row;
            uint4 v = make_uint4(0u, 0u, 0u, 0u);
            if (grow < NN)
                v = *(const uint4*)&g_xh[(size_t)grow * FIN + k0g + ch * 8];
            *(uint4*)&Xs[row][ch * 8] = v;
        }
        #pragma unroll
        for (int p = 0; p < 2; p++) {
            int idx = t + p * 256;           // 0..511
            int row = idx >> 3, ch = idx & 7;
            uint4 v = *(const uint4*)&g_w1h[(size_t)(k0g + row) * D1 + nb * 64 + ch * 8];
            *(uint4*)&Ws[row][ch * 8] = v;
        }
        __syncthreads();

        #pragma unroll
        for (int ks = 0; ks < 4; ks++) {
            int k0 = ks * 16;
            uint32_t a0, a1, a2, a3;
            {
                uint32_t ad = sptr(&Xs[wid * 16 + (lane & 15)][k0 + ((lane & 16) ? 8 : 0)]);
                asm volatile(
                    "ldmatrix.sync.aligned.m8n8.x4.shared.b16 {%0,%1,%2,%3}, [%4];"
                    : "=r"(a0), "=r"(a1), "=r"(a2), "=r"(a3) : "r"(ad));
            }
            #pragma unroll
            for (int ntp = 0; ntp < 4; ntp++) {   // pairs of n8-tiles
                uint32_t b0, b1, b2, b3;
                uint32_t bd = sptr(&Ws[k0 + (lane & 15)][ntp * 16 + ((lane & 16) ? 8 : 0)]);
                asm volatile(
                    "ldmatrix.sync.aligned.m8n8.x4.trans.shared.b16 {%0,%1,%2,%3}, [%4];"
                    : "=r"(b0), "=r"(b1), "=r"(b2), "=r"(b3) : "r"(bd));
                asm volatile(
                    "mma.sync.aligned.m16n8k16.row.col.f32.f16.f16.f32 "
                    "{%0,%1,%2,%3}, {%4,%5,%6,%7}, {%8,%9}, {%0,%1,%2,%3};"
                    : "+f"(acc[2 * ntp][0]), "+f"(acc[2 * ntp][1]),
                      "+f"(acc[2 * ntp][2]), "+f"(acc[2 * ntp][3])
                    : "r"(a0), "r"(a1), "r"(a2), "r"(a3), "r"(b0), "r"(b1));
                asm volatile(
                    "mma.sync.aligned.m16n8k16.row.col.f32.f16.f16.f32 "
                    "{%0,%1,%2,%3}, {%4,%5,%6,%7}, {%8,%9}, {%0,%1,%2,%3};"
                    : "+f"(acc[2 * ntp + 1][0]), "+f"(acc[2 * ntp + 1][1]),
                      "+f"(acc[2 * ntp + 1][2]), "+f"(acc[2 * ntp + 1][3])
                    : "r"(a0), "r"(a1), "r"(a2), "r"(a3), "r"(b2), "r"(b3));
            }
        }
    }

    // epilogue: store h1 fp16 + complete per-head coefs (BN==HID)
    int rlo = mB + wid * 16 + (lane >> 2);
    int rhi = rlo + 8;
    int q = lane & 3;
    float slo = 0.f, shi = 0.f, dlo = 0.f, dhi = 0.f;
    #pragma unroll
    for (int nt = 0; nt < 8; nt++) {
        int c = nt * 8 + 2 * q;
        slo += acc[nt][0] * sa[c] + acc[nt][1] * sa[c + 1];
        dlo += acc[nt][0] * sd[c] + acc[nt][1] * sd[c + 1];
        shi += acc[nt][2] * sa[c] + acc[nt][3] * sa[c + 1];
        dhi += acc[nt][2] * sd[c] + acc[nt][3] * sd[c + 1];
        if (rlo < NN)
            *(__half2*)&g_h1h[(size_t)rlo * D1 + nb * 64 + c] =
                __floats2half2_rn(acc[nt][0], acc[nt][1]);
        if (rhi < NN)
            *(__half2*)&g_h1h[(size_t)rhi * D1 + nb * 64 + c] =
                __floats2half2_rn(acc[nt][2], acc[nt][3]);
    }
    #pragma unroll
    for (int o = 1; o <= 2; o <<= 1) {
        slo += __shfl_xor_sync(0xffffffffu, slo, o);
        dlo += __shfl_xor_sync(0xffffffffu, dlo, o);
        shi += __shfl_xor_sync(0xffffffffu, shi, o);
        dhi += __shfl_xor_sync(0xffffffffu, dhi, o);
    }
    if (q == 0) {
        if (rlo < NN) { g_asrc1[rlo * 8 + nb] = slo; g_adst1[rlo * 8 + nb] = dlo; }
        if (rhi < NN) { g_asrc1[rhi * 8 + nb] = shi; g_adst1[rhi * 8 + nb] = dhi; }
    }
}

// -------- layer-1 aggregation: lean gather with precomputed weights --------
// chunk of 32 edges; weights loaded coalesced from g_ew.
__global__ void agg1_kernel(const float* __restrict__ b1) {
    int d = blockIdx.x;
    int t = threadIdx.x;   // 128
    __shared__ float salpha[256], sw[128], sinv[8];
    __shared__ int ssrc[32];
    int beg = g_rowptr[d];
    int deg = g_rowptr[d + 1] - beg;
    int h4 = t >> 4;                 // head of channels 4t..4t+3
    float4 acc = make_float4(0.f, 0.f, 0.f, 0.f);
    float wpart = 0.f;               // accumulates weights of head (t&7)

    for (int base = 0; base < deg; base += 32) {
        int cn = min(32, deg - base);
        __syncthreads();
        if (t < cn) ssrc[t] = g_csrc[beg + base + t];
        for (int j = t; j < cn * 8; j += 128) {     // coalesced weight load
            float w = g_ew[(size_t)(beg + base) * 8 + j];
            salpha[j] = w;
            wpart += w;                              // head (j&7) == (t&7)
        }
        __syncthreads();
        #pragma unroll 4
        for (int i = 0; i < cn; i++) {
            float a = salpha[i * 8 + h4];
            H4 v = *(const H4*)&g_h1h[(size_t)ssrc[i] * D1 + 4 * t];
            float2 f0 = __half22float2(v.a);
            float2 f1 = __half22float2(v.b);
            acc.x += a * f0.x; acc.y += a * f0.y;
            acc.z += a * f1.x; acc.w += a * f1.y;
        }
    }
    __syncthreads();
    sw[t] = wpart;
    __syncthreads();
    if (t < 8) {
        float s = 0.f;
        #pragma unroll
        for (int j = 0; j < 16; j++) s += sw[t + 8 * j];
        sinv[t] = 1.f / (s + 1e-16f);
    }
    __syncthreads();
    float inv = sinv[h4];
    float4 bv = *(const float4*)&b1[4 * t];
    float4 o;
    o.x = acc.x * inv + bv.x; o.x = o.x > 0.f ? o.x : expm1f(o.x);
    o.y = acc.y * inv + bv.y; o.y = o.y > 0.f ? o.y : expm1f(o.y);
    o.z = acc.z * inv + bv.z; o.z = o.z > 0.f ? o.z : expm1f(o.z);
    o.w = acc.w * inv + bv.w; o.w = o.w > 0.f ? o.w : expm1f(o.w);
    *(float4*)&g_h1act[(size_t)d * D1 + 4 * t] = o;
}

// -------- layer 2 GEMV + coefficients (warp per node, transposed W2 smem) --------
__global__ void node2_kernel(const float* __restrict__ W2,
                             const float* __restrict__ as2,
                             const float* __restrict__ ad2) {
    __shared__ float Ws[NC * D1];   // [j][c] transposed
    __shared__ float sas[NC], sad[NC];
    int t = threadIdx.x;
    for (int i = t; i < D1 * NC; i += 256) {
        int c = i / NC, j = i - c * NC;
        Ws[j * D1 + c] = W2[i];
    }
    if (t < NC) { sas[t] = as2[t]; sad[t] = ad2[t]; }
    __syncthreads();
    int n = blockIdx.x * 8 + (t >> 5);
    if (n >= NN) return;
    int lane = t & 31;
    const float* hp = &g_h1act[(size_t)n * D1];
    float acc[NC];
    #pragma unroll
    for (int j = 0; j < NC; j++) acc[j] = 0.f;
    for (int c = lane; c < D1; c += 32) {
        float xv = hp[c];
        #pragma unroll
        for (int j = 0; j < NC; j++) acc[j] += xv * Ws[j * D1 + c];
    }
    #pragma unroll
    for (int j = 0; j < NC; j++) acc[j] = wredsum(acc[j]);
    if (lane == 0) {
        float s = 0.f, dd = 0.f;
        #pragma unroll
        for (int j = 0; j < NC; j++) {
            g_h2[n * NC + j] = acc[j];
            s  += acc[j] * sas[j];
            dd += acc[j] * sad[j];
        }
        g_asrc2[n] = s;
        g_adst2[n] = dd;
    }
}

// -------- layer-2 edge softmax + aggregation (warp per dst, single pass) --------
__global__ void agg2_kernel(const float* __restrict__ b2) {
    int n = blockIdx.x * 8 + (threadIdx.x >> 5);
    if (n >= NN) return;
    int lane = threadIdx.x & 31;
    int beg = g_rowptr[n], end = g_rowptr[n + 1];
    float adv = g_adst2[n];
    float s = 0.f;
    float acc[NC];
    #pragma unroll
    for (int j = 0; j < NC; j++) acc[j] = 0.f;
    for (int i = beg + lane; i < end; i += 32) {
        int sn = g_csrc[i];
        float e = g_asrc2[sn] + adv;
        e = e > 0.f ? e : 0.2f * e;
        float w = __expf(e);
        s += w;
        const float* hp = &g_h2[sn * NC];
        #pragma unroll
        for (int j = 0; j < NC; j++) acc[j] += w * hp[j];
    }
    s = wredsum(s);
    #pragma unroll
    for (int j = 0; j < NC; j++) acc[j] = wredsum(acc[j]);
    if (lane == 0) {
        float inv = 1.f / (s + 1e-16f);
        #pragma unroll
        for (int j = 0; j < NC; j++)
            g_agg2[n * NC + j] = acc[j] * inv + b2[j];
    }
}

// -------- mean pooling per graph (batch is sorted) --------
__global__ void pool_kernel(const int* __restrict__ batch,
                            float* __restrict__ out) {
    int g = blockIdx.x;
    int t = threadIdx.x;
    int lo, hi;
    { int a = 0, b = NN;
      while (a < b) { int mid = (a + b) >> 1; if (batch[mid] < g) a = mid + 1; else b = mid; }
      lo = a; }
    { int a = lo, b = NN;
      while (a < b) { int mid = (a + b) >> 1; if (batch[mid] < g + 1) a = mid + 1; else b = mid; }
      hi = a; }
    __shared__ float red[NC];
    if (t < NC) red[t] = 0.f;
    __syncthreads();
    float acc[NC];
    #pragma unroll
    for (int j = 0; j < NC; j++) acc[j] = 0.f;
    for (int i = lo + t; i < hi; i += 256) {
        const float* hp = &g_agg2[i * NC];
        #pragma unroll
        for (int j = 0; j < NC; j++) acc[j] += hp[j];
    }
    #pragma unroll
    for (int j = 0; j < NC; j++) atomicAdd(&red[j], acc[j]);
    __syncthreads();
    int cnt = hi - lo;
    if (cnt < 1) cnt = 1;
    if (t < NC) out[g * NC + t] = red[t] / (float)cnt;
}

// -------- launcher --------
extern "C" void kernel_launch(void* const* d_in, const int* in_sizes, int n_in,
                              void* d_out, int out_size) {
    const float* x   = (const float*)d_in[0];
    const int*   ei  = (const int*)d_in[1];
    const int*   bat = (const int*)d_in[2];
    const float* W1  = (const float*)d_in[3];
    const float* as1 = (const float*)d_in[4];
    const float* ad1 = (const float*)d_in[5];
    const float* b1  = (const float*)d_in[6];
    const float* W2  = (const float*)d_in[7];
    const float* as2 = (const float*)d_in[8];
    const float* ad2 = (const float*)d_in[9];
    const float* b2  = (const float*)d_in[10];
    float* out = (float*)d_out;

    xh_kernel<<<(NN * FIN / 4 + 255) / 256, 256>>>(x);
    wh_kernel<<<(FIN * D1 / 4 + 255) / 256, 256>>>(W1);
    init_counts_kernel<<<(NN + 255) / 256, 256>>>();
    gemm1_tc_kernel<<<dim3(HEADS, (NN + 127) / 128), 256>>>(as1, ad1);
    count_kernel<<<(EE / 4 + 255) / 256, 256>>>(ei);
    scanA_kernel<<<NB, 256>>>();
    scanB_kernel<<<1, 128>>>();
    scanC_kernel<<<(NN + 255) / 256, 256>>>();
    scatter_kernel<<<(EE / 4 + 255) / 256, 256>>>(ei);
    ew_kernel<<<(ET * HEADS + 255) / 256, 256>>>();

    agg1_kernel<<<NN, 128>>>(b1);

    node2_kernel<<<(NN + 7) / 8, 256>>>(W2, as2, ad2);
    agg2_kernel<<<(NN + 7) / 8, 256>>>(b2);
    pool_kernel<<<NG, 256>>>(bat, out);
}

// round 11
// speedup vs baseline: 2.1588x; 1.0294x over previous
#include <cuda_runtime.h>
#include <cuda_fp16.h>
#include <math.h>
#include <stdint.h>

#define NN 20000
#define EE 320000
#define ET 340000      // EE + NN self loops
#define FIN 128
#define D1 512         // HEADS*HID
#define HEADS 8
#define HID 64
#define NC 10
#define NG 64
#define NB ((NN + 255) / 256)   // 79 scan blocks

// -------- scratch (device globals; no allocations allowed) --------
__device__ __half g_h1h[(size_t)NN * D1];    // layer1 features fp16 (gathered by agg1)
__device__ __half g_h1act[(size_t)NN * D1];  // elu(agg1 + b1), fp16
__device__ __half g_xh[(size_t)NN * FIN];    // x in fp16
__device__ __half g_w1h[FIN * D1];           // W1 in fp16
__device__ float  g_asrc1[NN * HEADS];
__device__ float  g_adst1[NN * HEADS];
__device__ float  g_ew[(size_t)ET * HEADS];  // per-(edge,head) softmax weights
__device__ float  g_h2[NN * NC];
__device__ float  g_asrc2[NN];
__device__ float  g_adst2[NN];
__device__ float  g_agg2[NN * NC];
__device__ int    g_counts[NN];
__device__ int    g_rowptr[NN + 1];
__device__ int    g_wptr[NN];
__device__ int    g_csrc[ET];
__device__ int    g_edst[ET];
__device__ int    g_bsum[NB];
__device__ int    g_boff[NB];

struct alignas(8) H4 { __half2 a, b; };   // 4 halfs, one LDG/STG.64

__device__ __forceinline__ float wredsum(float v) {
    #pragma unroll
    for (int o = 16; o; o >>= 1) v += __shfl_xor_sync(0xffffffffu, v, o);
    return v;
}
__device__ __forceinline__ uint32_t sptr(const void* p) {
    return (uint32_t)__cvta_generic_to_shared(p);
}

// -------- fp16 converts --------
__global__ void xh_kernel(const float* __restrict__ X) {
    int i = blockIdx.x * 256 + threadIdx.x;          // one float4
    if (i >= NN * FIN / 4) return;
    float4 v = ((const float4*)X)[i];
    H4 pk;
    pk.a = __floats2half2_rn(v.x, v.y);
    pk.b = __floats2half2_rn(v.z, v.w);
    ((H4*)g_xh)[i] = pk;
}
__global__ void wh_kernel(const float* __restrict__ W) {
    int i = blockIdx.x * 256 + threadIdx.x;
    if (i >= FIN * D1 / 4) return;
    float4 v = ((const float4*)W)[i];
    H4 pk;
    pk.a = __floats2half2_rn(v.x, v.y);
    pk.b = __floats2half2_rn(v.z, v.w);
    ((H4*)g_w1h)[i] = pk;
}

// -------- CSR build --------
__global__ void init_counts_kernel() {
    int i = blockIdx.x * blockDim.x + threadIdx.x;
    if (i < NN) g_counts[i] = 1;     // self-loop pre-counted
}
__global__ void count_kernel(const int* __restrict__ ei) {
    int i = blockIdx.x * blockDim.x + threadIdx.x;
    if (i >= EE / 4) return;
    int4 d = ((const int4*)(ei + EE))[i];
    atomicAdd(&g_counts[d.x], 1);
    atomicAdd(&g_counts[d.y], 1);
    atomicAdd(&g_counts[d.z], 1);
    atomicAdd(&g_counts[d.w], 1);
}
// parallel scan, phase A: per-256-node block exclusive scan + block sum
__global__ void scanA_kernel() {
    __shared__ int sh[256];
    int t = threadIdx.x;
    int n = blockIdx.x * 256 + t;
    int c = (n < NN) ? g_counts[n] : 0;
    sh[t] = c;
    __syncthreads();
    #pragma unroll
    for (int off = 1; off < 256; off <<= 1) {
        int v = (t >= off) ? sh[t - off] : 0;
        __syncthreads();
        sh[t] += v;
        __syncthreads();
    }
    if (n < NN) g_rowptr[n] = sh[t] - c;   // block-local exclusive prefix
    if (t == 255) g_bsum[blockIdx.x] = sh[255];
}
// phase B: single block scans the 79 block sums
__global__ void scanB_kernel() {
    __shared__ int sh[128];
    int t = threadIdx.x;
    int v = (t < NB) ? g_bsum[t] : 0;
    sh[t] = v;
    __syncthreads();
    #pragma unroll
    for (int off = 1; off < 128; off <<= 1) {
        int u = (t >= off) ? sh[t - off] : 0;
        __syncthreads();
        sh[t] += u;
        __syncthreads();
    }
    if (t < NB) g_boff[t] = sh[t] - v;     // exclusive
}
// phase C: globalize rowptr, seed self-loop slot, init wptr
__global__ void scanC_kernel() {
    int n = blockIdx.x * blockDim.x + threadIdx.x;
    if (n >= NN) return;
    int r = g_rowptr[n] + g_boff[n >> 8];
    g_rowptr[n] = r;
    g_wptr[n] = r + 1;
    g_csrc[r] = n;
    g_edst[r] = n;
    if (n == 0) g_rowptr[NN] = ET;
}
__global__ void scatter_kernel(const int* __restrict__ ei) {
    int i = blockIdx.x * blockDim.x + threadIdx.x;
    if (i >= EE / 4) return;
    int4 s = ((const int4*)ei)[i];
    int4 d = ((const int4*)(ei + EE))[i];
    int p0 = atomicAdd(&g_wptr[d.x], 1);
    int p1 = atomicAdd(&g_wptr[d.y], 1);
    int p2 = atomicAdd(&g_wptr[d.z], 1);
    int p3 = atomicAdd(&g_wptr[d.w], 1);
    g_csrc[p0] = s.x;  g_edst[p0] = d.x;
    g_csrc[p1] = s.y;  g_edst[p1] = d.y;
    g_csrc[p2] = s.z;  g_edst[p2] = d.z;
    g_csrc[p3] = s.w;  g_edst[p3] = d.w;
}

// -------- edge softmax weights --------
__global__ void ew_kernel() {
    int idx = blockIdx.x * 256 + threadIdx.x;   // e*8+h
    if (idx >= ET * HEADS) return;
    int e = idx >> 3, h = idx & 7;
    int src = g_csrc[e], dst = g_edst[e];
    float v = g_asrc1[src * 8 + h] + g_adst1[dst * 8 + h];
    v = v > 0.f ? v : 0.2f * v;
    g_ew[idx] = __expf(v);
}

// -------- tensor-core GEMM1 + fused attention coefs (single-phase loads) --------
__global__ __launch_bounds__(256, 2)
void gemm1_tc_kernel(const float* __restrict__ asv,
                     const float* __restrict__ adv) {
    __shared__ __half Xs[128][136];  // full K=128, pad 8: LDSM conflict-free
    __shared__ __half Ws[128][72];   // full K rows x 64 cols
    __shared__ float sa[64], sd[64];
    int t = threadIdx.x, lane = t & 31, wid = t >> 5;
    int nb = blockIdx.x;             // head / 64-col block
    int mb = blockIdx.y;
    int mB = mb * 128;
    if (t < 64) { sa[t] = asv[nb * 64 + t]; sd[t] = adv[nb * 64 + t]; }

    // load ALL of X tile (128x128 halfs) and W tile (128x64 halfs) up front
    #pragma unroll
    for (int p = 0; p < 8; p++) {
        int idx = t + p * 256;           // 0..2047
        int row = idx >> 4, ch = idx & 15;
        int grow = mB + row;
        uint4 v = make_uint4(0u, 0u, 0u, 0u);
        if (grow < NN)
            v = *(const uint4*)&g_xh[(size_t)grow * FIN + ch * 8];
        *(uint4*)&Xs[row][ch * 8] = v;
    }
    #pragma unroll
    for (int p = 0; p < 4; p++) {
        int idx = t + p * 256;           // 0..1023
        int row = idx >> 3, ch = idx & 7;
        uint4 v = *(const uint4*)&g_w1h[(size_t)row * D1 + nb * 64 + ch * 8];
        *(uint4*)&Ws[row][ch * 8] = v;
    }
    __syncthreads();

    float acc[8][4];
    #pragma unroll
    for (int i = 0; i < 8; i++)
        #pragma unroll
        for (int j = 0; j < 4; j++) acc[i][j] = 0.f;

    #pragma unroll
    for (int ks = 0; ks < 8; ks++) {
        int k0 = ks * 16;
        uint32_t a0, a1, a2, a3;
        {
            uint32_t ad = sptr(&Xs[wid * 16 + (lane & 15)][k0 + ((lane & 16) ? 8 : 0)]);
            asm volatile(
                "ldmatrix.sync.aligned.m8n8.x4.shared.b16 {%0,%1,%2,%3}, [%4];"
                : "=r"(a0), "=r"(a1), "=r"(a2), "=r"(a3) : "r"(ad));
        }
        #pragma unroll
        for (int ntp = 0; ntp < 4; ntp++) {   // pairs of n8-tiles
            uint32_t b0, b1, b2, b3;
            uint32_t bd = sptr(&Ws[k0 + (lane & 15)][ntp * 16 + ((lane & 16) ? 8 : 0)]);
            asm volatile(
                "ldmatrix.sync.aligned.m8n8.x4.trans.shared.b16 {%0,%1,%2,%3}, [%4];"
                : "=r"(b0), "=r"(b1), "=r"(b2), "=r"(b3) : "r"(bd));
            asm volatile(
                "mma.sync.aligned.m16n8k16.row.col.f32.f16.f16.f32 "
                "{%0,%1,%2,%3}, {%4,%5,%6,%7}, {%8,%9}, {%0,%1,%2,%3};"
                : "+f"(acc[2 * ntp][0]), "+f"(acc[2 * ntp][1]),
                  "+f"(acc[2 * ntp][2]), "+f"(acc[2 * ntp][3])
                : "r"(a0), "r"(a1), "r"(a2), "r"(a3), "r"(b0), "r"(b1));
            asm volatile(
                "mma.sync.aligned.m16n8k16.row.col.f32.f16.f16.f32 "
                "{%0,%1,%2,%3}, {%4,%5,%6,%7}, {%8,%9}, {%0,%1,%2,%3};"
                : "+f"(acc[2 * ntp + 1][0]), "+f"(acc[2 * ntp + 1][1]),
                  "+f"(acc[2 * ntp + 1][2]), "+f"(acc[2 * ntp + 1][3])
                : "r"(a0), "r"(a1), "r"(a2), "r"(a3), "r"(b2), "r"(b3));
        }
    }

    // epilogue: store h1 fp16 + complete per-head coefs (BN==HID)
    int rlo = mB + wid * 16 + (lane >> 2);
    int rhi = rlo + 8;
    int q = lane & 3;
    float slo = 0.f, shi = 0.f, dlo = 0.f, dhi = 0.f;
    #pragma unroll
    for (int nt = 0; nt < 8; nt++) {
        int c = nt * 8 + 2 * q;
        slo += acc[nt][0] * sa[c] + acc[nt][1] * sa[c + 1];
        dlo += acc[nt][0] * sd[c] + acc[nt][1] * sd[c + 1];
        shi += acc[nt][2] * sa[c] + acc[nt][3] * sa[c + 1];
        dhi += acc[nt][2] * sd[c] + acc[nt][3] * sd[c + 1];
        if (rlo < NN)
            *(__half2*)&g_h1h[(size_t)rlo * D1 + nb * 64 + c] =
                __floats2half2_rn(acc[nt][0], acc[nt][1]);
        if (rhi < NN)
            *(__half2*)&g_h1h[(size_t)rhi * D1 + nb * 64 + c] =
                __floats2half2_rn(acc[nt][2], acc[nt][3]);
    }
    #pragma unroll
    for (int o = 1; o <= 2; o <<= 1) {
        slo += __shfl_xor_sync(0xffffffffu, slo, o);
        dlo += __shfl_xor_sync(0xffffffffu, dlo, o);
        shi += __shfl_xor_sync(0xffffffffu, shi, o);
        dhi += __shfl_xor_sync(0xffffffffu, dhi, o);
    }
    if (q == 0) {
        if (rlo < NN) { g_asrc1[rlo * 8 + nb] = slo; g_adst1[rlo * 8 + nb] = dlo; }
        if (rhi < NN) { g_asrc1[rhi * 8 + nb] = shi; g_adst1[rhi * 8 + nb] = dhi; }
    }
}

// -------- layer-1 aggregation: lean gather with precomputed weights --------
__global__ void agg1_kernel(const float* __restrict__ b1) {
    int d = blockIdx.x;
    int t = threadIdx.x;   // 128
    __shared__ float salpha[256], sw[128], sinv[8];
    __shared__ int ssrc[32];
    int beg = g_rowptr[d];
    int deg = g_rowptr[d + 1] - beg;
    int h4 = t >> 4;                 // head of channels 4t..4t+3
    float4 acc = make_float4(0.f, 0.f, 0.f, 0.f);
    float wpart = 0.f;               // accumulates weights of head (t&7)

    for (int base = 0; base < deg; base += 32) {
        int cn = min(32, deg - base);
        __syncthreads();
        if (t < cn) ssrc[t] = g_csrc[beg + base + t];
        for (int j = t; j < cn * 8; j += 128) {     // coalesced weight load
            float w = g_ew[(size_t)(beg + base) * 8 + j];
            salpha[j] = w;
            wpart += w;                              // head (j&7) == (t&7)
        }
        __syncthreads();
        #pragma unroll 4
        for (int i = 0; i < cn; i++) {
            float a = salpha[i * 8 + h4];
            H4 v = *(const H4*)&g_h1h[(size_t)ssrc[i] * D1 + 4 * t];
            float2 f0 = __half22float2(v.a);
            float2 f1 = __half22float2(v.b);
            acc.x += a * f0.x; acc.y += a * f0.y;
            acc.z += a * f1.x; acc.w += a * f1.y;
        }
    }
    __syncthreads();
    sw[t] = wpart;
    __syncthreads();
    if (t < 8) {
        float s = 0.f;
        #pragma unroll
        for (int j = 0; j < 16; j++) s += sw[t + 8 * j];
        sinv[t] = 1.f / (s + 1e-16f);
    }
    __syncthreads();
    float inv = sinv[h4];
    float4 bv = *(const float4*)&b1[4 * t];
    float o0, o1, o2, o3;
    o0 = acc.x * inv + bv.x; o0 = o0 > 0.f ? o0 : expm1f(o0);
    o1 = acc.y * inv + bv.y; o1 = o1 > 0.f ? o1 : expm1f(o1);
    o2 = acc.z * inv + bv.z; o2 = o2 > 0.f ? o2 : expm1f(o2);
    o3 = acc.w * inv + bv.w; o3 = o3 > 0.f ? o3 : expm1f(o3);
    H4 pk;
    pk.a = __floats2half2_rn(o0, o1);
    pk.b = __floats2half2_rn(o2, o3);
    *(H4*)&g_h1act[(size_t)d * D1 + 4 * t] = pk;
}

// -------- layer 2 GEMV + coefficients (warp per node, transposed W2 smem) --------
__global__ void node2_kernel(const float* __restrict__ W2,
                             const float* __restrict__ as2,
                             const float* __restrict__ ad2) {
    __shared__ float Ws[NC * D1];   // [j][c] transposed
    __shared__ float sas[NC], sad[NC];
    int t = threadIdx.x;
    for (int i = t; i < D1 * NC; i += 256) {
        int c = i / NC, j = i - c * NC;
        Ws[j * D1 + c] = W2[i];
    }
    if (t < NC) { sas[t] = as2[t]; sad[t] = ad2[t]; }
    __syncthreads();
    int n = blockIdx.x * 8 + (t >> 5);
    if (n >= NN) return;
    int lane = t & 31;
    const __half* hp = &g_h1act[(size_t)n * D1];
    float acc[NC];
    #pragma unroll
    for (int j = 0; j < NC; j++) acc[j] = 0.f;
    for (int c = lane; c < D1; c += 32) {
        float xv = __half2float(hp[c]);
        #pragma unroll
        for (int j = 0; j < NC; j++) acc[j] += xv * Ws[j * D1 + c];
    }
    #pragma unroll
    for (int j = 0; j < NC; j++) acc[j] = wredsum(acc[j]);
    if (lane == 0) {
        float s = 0.f, dd = 0.f;
        #pragma unroll
        for (int j = 0; j < NC; j++) {
            g_h2[n * NC + j] = acc[j];
            s  += acc[j] * sas[j];
            dd += acc[j] * sad[j];
        }
        g_asrc2[n] = s;
        g_adst2[n] = dd;
    }
}

// -------- layer-2 edge softmax + aggregation (warp per dst, single pass) --------
__global__ void agg2_kernel(const float* __restrict__ b2) {
    int n = blockIdx.x * 8 + (threadIdx.x >> 5);
    if (n >= NN) return;
    int lane = threadIdx.x & 31;
    int beg = g_rowptr[n], end = g_rowptr[n + 1];
    float adv = g_adst2[n];
    float s = 0.f;
    float acc[NC];
    #pragma unroll
    for (int j = 0; j < NC; j++) acc[j] = 0.f;
    for (int i = beg + lane; i < end; i += 32) {
        int sn = g_csrc[i];
        float e = g_asrc2[sn] + adv;
        e = e > 0.f ? e : 0.2f * e;
        float w = __expf(e);
        s += w;
        const float* hp = &g_h2[sn * NC];
        #pragma unroll
        for (int j = 0; j < NC; j++) acc[j] += w * hp[j];
    }
    s = wredsum(s);
    #pragma unroll
    for (int j = 0; j < NC; j++) acc[j] = wredsum(acc[j]);
    if (lane == 0) {
        float inv = 1.f / (s + 1e-16f);
        #pragma unroll
        for (int j = 0; j < NC; j++)
            g_agg2[n * NC + j] = acc[j] * inv + b2[j];
    }
}

// -------- mean pooling per graph (batch is sorted) --------
__global__ void pool_kernel(const int* __restrict__ batch,
                            float* __restrict__ out) {
    int g = blockIdx.x;
    int t = threadIdx.x;
    int lo, hi;
    { int a = 0, b = NN;
      while (a < b) { int mid = (a + b) >> 1; if (batch[mid] < g) a = mid + 1; else b = mid; }
      lo = a; }
    { int a = lo, b = NN;
      while (a < b) { int mid = (a + b) >> 1; if (batch[mid] < g + 1) a = mid + 1; else b = mid; }
      hi = a; }
    __shared__ float red[NC];
    if (t < NC) red[t] = 0.f;
    __syncthreads();
    float acc[NC];
    #pragma unroll
    for (int j = 0; j < NC; j++) acc[j] = 0.f;
    for (int i = lo + t; i < hi; i += 256) {
        const float* hp = &g_agg2[i * NC];
        #pragma unroll
        for (int j = 0; j < NC; j++) acc[j] += hp[j];
    }
    #pragma unroll
    for (int j = 0; j < NC; j++) atomicAdd(&red[j], acc[j]);
    __syncthreads();
    int cnt = hi - lo;
    if (cnt < 1) cnt = 1;
    if (t < NC) out[g * NC + t] = red[t] / (float)cnt;
}

// -------- launcher --------
extern "C" void kernel_launch(void* const* d_in, const int* in_sizes, int n_in,
                              void* d_out, int out_size) {
    const float* x   = (const float*)d_in[0];
    const int*   ei  = (const int*)d_in[1];
    const int*   bat = (const int*)d_in[2];
    const float* W1  = (const float*)d_in[3];
    const float* as1 = (const float*)d_in[4];
    const float* ad1 = (const float*)d_in[5];
    const float* b1  = (const float*)d_in[6];
    const float* W2  = (const float*)d_in[7];
    const float* as2 = (const float*)d_in[8];
    const float* ad2 = (const float*)d_in[9];
    const float* b2  = (const float*)d_in[10];
    float* out = (float*)d_out;

    xh_kernel<<<(NN * FIN / 4 + 255) / 256, 256>>>(x);
    wh_kernel<<<(FIN * D1 / 4 + 255) / 256, 256>>>(W1);
    init_counts_kernel<<<(NN + 255) / 256, 256>>>();
    gemm1_tc_kernel<<<dim3(HEADS, (NN + 127) / 128), 256>>>(as1, ad1);
    count_kernel<<<(EE / 4 + 255) / 256, 256>>>(ei);
    scanA_kernel<<<NB, 256>>>();
    scanB_kernel<<<1, 128>>>();
    scanC_kernel<<<(NN + 255) / 256, 256>>>();
    scatter_kernel<<<(EE / 4 + 255) / 256, 256>>>(ei);
    ew_kernel<<<(ET * HEADS + 255) / 256, 256>>>();

    agg1_kernel<<<NN, 128>>>(b1);

    node2_kernel<<<(NN + 7) / 8, 256>>>(W2, as2, ad2);
    agg2_kernel<<<(NN + 7) / 8, 256>>>(b2);
    pool_kernel<<<NG, 256>>>(bat, out);
}

// round 12
// speedup vs baseline: 2.2071x; 1.0224x over previous
#include <cuda_runtime.h>
#include <cuda_fp16.h>
#include <math.h>
#include <stdint.h>

#define NN 20000
#define EE 320000
#define ET 340000      // EE + NN self loops
#define FIN 128
#define D1 512         // HEADS*HID
#define HEADS 8
#define HID 64
#define NC 10
#define NG 64
#define NB ((NN + 255) / 256)   // 79 scan blocks
#define LOG2E 1.4426950408889634f

// -------- scratch (device globals; no allocations allowed) --------
__device__ __half g_h1h[(size_t)NN * D1];    // layer1 features fp16
__device__ __half g_h1act[(size_t)NN * D1];  // elu(agg1 + b1), fp16
__device__ __half g_xh[(size_t)NN * FIN];    // x in fp16
__device__ __half g_w1h[FIN * D1];           // W1 in fp16
__device__ float  g_asrc1[NN * HEADS];
__device__ float  g_adst1[NN * HEADS];
__device__ __half g_ewh[(size_t)ET * HEADS]; // per-(edge,head) weights, fp16
__device__ float  g_h2[NN * NC];
__device__ float  g_asrc2[NN];
__device__ float  g_adst2[NN];
__device__ float  g_agg2[NN * NC];
__device__ int    g_counts[NN];   // zero-init; scanC resets to 0 each call
__device__ int    g_rowptr[NN + 1];
__device__ int    g_wptr[NN];
__device__ int    g_csrc[ET];
__device__ int    g_bsum[NB];
__device__ int    g_boff[NB];

struct alignas(8) H4 { __half2 a, b; };   // 4 halfs, one LDG/STG.64

__device__ __forceinline__ float wredsum(float v) {
    #pragma unroll
    for (int o = 16; o; o >>= 1) v += __shfl_xor_sync(0xffffffffu, v, o);
    return v;
}
__device__ __forceinline__ uint32_t sptr(const void* p) {
    return (uint32_t)__cvta_generic_to_shared(p);
}
// exp(a),exp(b) -> packed half2 (one MUFU op for two exps)
__device__ __forceinline__ uint32_t exp2_h2(float a, float b) {
    union { __half2 h; uint32_t u; } in, out;
    in.h = __floats2half2_rn(a * LOG2E, b * LOG2E);
    asm("ex2.approx.f16x2 %0, %1;" : "=r"(out.u) : "r"(in.u));
    return out.u;
}
__device__ __forceinline__ float lrelu(float v) {
    return v > 0.f ? v : 0.2f * v;
}

// -------- prep: x->fp16, W1->fp16, degree count (counts stay 0-based) --------
__global__ void prep_kernel(const float* __restrict__ X,
                            const float* __restrict__ W,
                            const int* __restrict__ ei) {
    int i = blockIdx.x * 256 + threadIdx.x;
    if (i < NN * FIN / 4) {
        float4 v = ((const float4*)X)[i];
        H4 pk;
        pk.a = __floats2half2_rn(v.x, v.y);
        pk.b = __floats2half2_rn(v.z, v.w);
        ((H4*)g_xh)[i] = pk;
    }
    if (i < FIN * D1 / 4) {
        float4 v = ((const float4*)W)[i];
        H4 pk;
        pk.a = __floats2half2_rn(v.x, v.y);
        pk.b = __floats2half2_rn(v.z, v.w);
        ((H4*)g_w1h)[i] = pk;
    }
    if (i < EE / 4) {
        int4 d = ((const int4*)(ei + EE))[i];
        atomicAdd(&g_counts[d.x], 1);
        atomicAdd(&g_counts[d.y], 1);
        atomicAdd(&g_counts[d.z], 1);
        atomicAdd(&g_counts[d.w], 1);
    }
}

// -------- scan phase A: per-block exclusive scan of (counts+1) --------
__global__ void scanA_kernel() {
    __shared__ int sh[256];
    int t = threadIdx.x;
    int n = blockIdx.x * 256 + t;
    int c = (n < NN) ? (g_counts[n] + 1) : 0;   // +1 = self loop
    sh[t] = c;
    __syncthreads();
    #pragma unroll
    for (int off = 1; off < 256; off <<= 1) {
        int v = (t >= off) ? sh[t - off] : 0;
        __syncthreads();
        sh[t] += v;
        __syncthreads();
    }
    if (n < NN) g_rowptr[n] = sh[t] - c;
    if (t == 255) g_bsum[blockIdx.x] = sh[255];
}
// phase B: single block scans block sums
__global__ void scanB_kernel() {
    __shared__ int sh[128];
    int t = threadIdx.x;
    int v = (t < NB) ? g_bsum[t] : 0;
    sh[t] = v;
    __syncthreads();
    #pragma unroll
    for (int off = 1; off < 128; off <<= 1) {
        int u = (t >= off) ? sh[t - off] : 0;
        __syncthreads();
        sh[t] += u;
        __syncthreads();
    }
    if (t < NB) g_boff[t] = sh[t] - v;
}
// phase C: globalize rowptr, seed self-loop slot + its weights, reset counts
__global__ void scanC_kernel() {
    int n = blockIdx.x * blockDim.x + threadIdx.x;
    if (n >= NN) return;
    int r = g_rowptr[n] + g_boff[n >> 8];
    g_rowptr[n] = r;
    g_wptr[n] = r + 1;
    g_csrc[r] = n;
    g_counts[n] = 0;   // ready for next graph replay
    float4 s0 = *(const float4*)&g_asrc1[n * 8];
    float4 s1 = *(const float4*)&g_asrc1[n * 8 + 4];
    float4 d0 = *(const float4*)&g_adst1[n * 8];
    float4 d1 = *(const float4*)&g_adst1[n * 8 + 4];
    uint4 w;
    w.x = exp2_h2(lrelu(s0.x + d0.x), lrelu(s0.y + d0.y));
    w.y = exp2_h2(lrelu(s0.z + d0.z), lrelu(s0.w + d0.w));
    w.z = exp2_h2(lrelu(s1.x + d1.x), lrelu(s1.y + d1.y));
    w.w = exp2_h2(lrelu(s1.z + d1.z), lrelu(s1.w + d1.w));
    *(uint4*)&g_ewh[(size_t)r * 8] = w;
    if (n == 0) g_rowptr[NN] = ET;
}

// -------- scatter + fused edge weights --------
__global__ void scatter_ew_kernel(const int* __restrict__ ei) {
    int i = blockIdx.x * blockDim.x + threadIdx.x;
    if (i >= EE / 4) return;
    int4 s = ((const int4*)ei)[i];
    int4 d = ((const int4*)(ei + EE))[i];
    int src[4] = {s.x, s.y, s.z, s.w};
    int dst[4] = {d.x, d.y, d.z, d.w};
    #pragma unroll
    for (int k = 0; k < 4; k++) {
        int p = atomicAdd(&g_wptr[dst[k]], 1);
        g_csrc[p] = src[k];
        float4 s0 = *(const float4*)&g_asrc1[src[k] * 8];
        float4 s1 = *(const float4*)&g_asrc1[src[k] * 8 + 4];
        float4 d0 = *(const float4*)&g_adst1[dst[k] * 8];
        float4 d1 = *(const float4*)&g_adst1[dst[k] * 8 + 4];
        uint4 w;
        w.x = exp2_h2(lrelu(s0.x + d0.x), lrelu(s0.y + d0.y));
        w.y = exp2_h2(lrelu(s0.z + d0.z), lrelu(s0.w + d0.w));
        w.z = exp2_h2(lrelu(s1.x + d1.x), lrelu(s1.y + d1.y));
        w.w = exp2_h2(lrelu(s1.z + d1.z), lrelu(s1.w + d1.w));
        *(uint4*)&g_ewh[(size_t)p * 8] = w;
    }
}

// -------- tensor-core GEMM1 + fused attention coefs (single-phase loads) --------
__global__ __launch_bounds__(256, 2)
void gemm1_tc_kernel(const float* __restrict__ asv,
                     const float* __restrict__ adv) {
    __shared__ __half Xs[128][136];  // full K=128, pad 8: LDSM conflict-free
    __shared__ __half Ws[128][72];   // full K rows x 64 cols
    __shared__ float sa[64], sd[64];
    int t = threadIdx.x, lane = t & 31, wid = t >> 5;
    int nb = blockIdx.x;             // head / 64-col block
    int mb = blockIdx.y;
    int mB = mb * 128;
    if (t < 64) { sa[t] = asv[nb * 64 + t]; sd[t] = adv[nb * 64 + t]; }

    #pragma unroll
    for (int p = 0; p < 8; p++) {
        int idx = t + p * 256;           // 0..2047
        int row = idx >> 4, ch = idx & 15;
        int grow = mB + row;
        uint4 v = make_uint4(0u, 0u, 0u, 0u);
        if (grow < NN)
            v = *(const uint4*)&g_xh[(size_t)grow * FIN + ch * 8];
        *(uint4*)&Xs[row][ch * 8] = v;
    }
    #pragma unroll
    for (int p = 0; p < 4; p++) {
        int idx = t + p * 256;           // 0..1023
        int row = idx >> 3, ch = idx & 7;
        uint4 v = *(const uint4*)&g_w1h[(size_t)row * D1 + nb * 64 + ch * 8];
        *(uint4*)&Ws[row][ch * 8] = v;
    }
    __syncthreads();

    float acc[8][4];
    #pragma unroll
    for (int i = 0; i < 8; i++)
        #pragma unroll
        for (int j = 0; j < 4; j++) acc[i][j] = 0.f;

    #pragma unroll
    for (int ks = 0; ks < 8; ks++) {
        int k0 = ks * 16;
        uint32_t a0, a1, a2, a3;
        {
            uint32_t ad = sptr(&Xs[wid * 16 + (lane & 15)][k0 + ((lane & 16) ? 8 : 0)]);
            asm volatile(
                "ldmatrix.sync.aligned.m8n8.x4.shared.b16 {%0,%1,%2,%3}, [%4];"
                : "=r"(a0), "=r"(a1), "=r"(a2), "=r"(a3) : "r"(ad));
        }
        #pragma unroll
        for (int ntp = 0; ntp < 4; ntp++) {
            uint32_t b0, b1, b2, b3;
            uint32_t bd = sptr(&Ws[k0 + (lane & 15)][ntp * 16 + ((lane & 16) ? 8 : 0)]);
            asm volatile(
                "ldmatrix.sync.aligned.m8n8.x4.trans.shared.b16 {%0,%1,%2,%3}, [%4];"
                : "=r"(b0), "=r"(b1), "=r"(b2), "=r"(b3) : "r"(bd));
            asm volatile(
                "mma.sync.aligned.m16n8k16.row.col.f32.f16.f16.f32 "
                "{%0,%1,%2,%3}, {%4,%5,%6,%7}, {%8,%9}, {%0,%1,%2,%3};"
                : "+f"(acc[2 * ntp][0]), "+f"(acc[2 * ntp][1]),
                  "+f"(acc[2 * ntp][2]), "+f"(acc[2 * ntp][3])
                : "r"(a0), "r"(a1), "r"(a2), "r"(a3), "r"(b0), "r"(b1));
            asm volatile(
                "mma.sync.aligned.m16n8k16.row.col.f32.f16.f16.f32 "
                "{%0,%1,%2,%3}, {%4,%5,%6,%7}, {%8,%9}, {%0,%1,%2,%3};"
                : "+f"(acc[2 * ntp + 1][0]), "+f"(acc[2 * ntp + 1][1]),
                  "+f"(acc[2 * ntp + 1][2]), "+f"(acc[2 * ntp + 1][3])
                : "r"(a0), "r"(a1), "r"(a2), "r"(a3), "r"(b2), "r"(b3));
        }
    }

    // epilogue: store h1 fp16 + complete per-head coefs (BN==HID)
    int rlo = mB + wid * 16 + (lane >> 2);
    int rhi = rlo + 8;
    int q = lane & 3;
    float slo = 0.f, shi = 0.f, dlo = 0.f, dhi = 0.f;
    #pragma unroll
    for (int nt = 0; nt < 8; nt++) {
        int c = nt * 8 + 2 * q;
        slo += acc[nt][0] * sa[c] + acc[nt][1] * sa[c + 1];
        dlo += acc[nt][0] * sd[c] + acc[nt][1] * sd[c + 1];
        shi += acc[nt][2] * sa[c] + acc[nt][3] * sa[c + 1];
        dhi += acc[nt][2] * sd[c] + acc[nt][3] * sd[c + 1];
        if (rlo < NN)
            *(__half2*)&g_h1h[(size_t)rlo * D1 + nb * 64 + c] =
                __floats2half2_rn(acc[nt][0], acc[nt][1]);
        if (rhi < NN)
            *(__half2*)&g_h1h[(size_t)rhi * D1 + nb * 64 + c] =
                __floats2half2_rn(acc[nt][2], acc[nt][3]);
    }
    #pragma unroll
    for (int o = 1; o <= 2; o <<= 1) {
        slo += __shfl_xor_sync(0xffffffffu, slo, o);
        dlo += __shfl_xor_sync(0xffffffffu, dlo, o);
        shi += __shfl_xor_sync(0xffffffffu, shi, o);
        dhi += __shfl_xor_sync(0xffffffffu, dhi, o);
    }
    if (q == 0) {
        if (rlo < NN) { g_asrc1[rlo * 8 + nb] = slo; g_adst1[rlo * 8 + nb] = dlo; }
        if (rhi < NN) { g_asrc1[rhi * 8 + nb] = shi; g_adst1[rhi * 8 + nb] = dhi; }
    }
}

// -------- layer-1 aggregation: barrier-free, 2 nodes per 256-thread block --------
// Thread t (of 128 per node) owns channels 4t..4t+3 (head h4=t>>4) and reads
// its own weight + denominator directly; no shared memory, no __syncthreads.
__global__ void agg1_kernel(const float* __restrict__ b1) {
    int tt = threadIdx.x;
    int t = tt & 127;
    int d = blockIdx.x * 2 + (tt >> 7);   // NN even
    int beg = g_rowptr[d];
    int end = g_rowptr[d + 1];
    int h4 = t >> 4;
    float ax = 0.f, ay = 0.f, az = 0.f, aw = 0.f, wsum = 0.f;
    #pragma unroll 4
    for (int i = beg; i < end; i++) {
        int sn = g_csrc[i];                                   // broadcast
        float a = __half2float(g_ewh[(size_t)i * 8 + h4]);    // 2 addrs/warp
        H4 v = *(const H4*)&g_h1h[(size_t)sn * D1 + 4 * t];
        float2 f0 = __half22float2(v.a);
        float2 f1 = __half22float2(v.b);
        ax += a * f0.x; ay += a * f0.y;
        az += a * f1.x; aw += a * f1.y;
        wsum += a;
    }
    float inv = 1.f / (wsum + 1e-16f);
    float4 bv = *(const float4*)&b1[4 * t];
    float o0, o1, o2, o3;
    o0 = ax * inv + bv.x; o0 = o0 > 0.f ? o0 : expm1f(o0);
    o1 = ay * inv + bv.y; o1 = o1 > 0.f ? o1 : expm1f(o1);
    o2 = az * inv + bv.z; o2 = o2 > 0.f ? o2 : expm1f(o2);
    o3 = aw * inv + bv.w; o3 = o3 > 0.f ? o3 : expm1f(o3);
    H4 pk;
    pk.a = __floats2half2_rn(o0, o1);
    pk.b = __floats2half2_rn(o2, o3);
    *(H4*)&g_h1act[(size_t)d * D1 + 4 * t] = pk;
}

// -------- layer 2 GEMV + coefficients (warp per node, transposed W2 smem) --------
__global__ void node2_kernel(const float* __restrict__ W2,
                             const float* __restrict__ as2,
                             const float* __restrict__ ad2) {
    __shared__ float Ws[NC * D1];   // [j][c] transposed
    __shared__ float sas[NC], sad[NC];
    int t = threadIdx.x;
    for (int i = t; i < D1 * NC; i += 256) {
        int c = i / NC, j = i - c * NC;
        Ws[j * D1 + c] = W2[i];
    }
    if (t < NC) { sas[t] = as2[t]; sad[t] = ad2[t]; }
    __syncthreads();
    int n = blockIdx.x * 8 + (t >> 5);
    if (n >= NN) return;
    int lane = t & 31;
    const __half* hp = &g_h1act[(size_t)n * D1];
    float acc[NC];
    #pragma unroll
    for (int j = 0; j < NC; j++) acc[j] = 0.f;
    for (int c = lane; c < D1; c += 32) {
        float xv = __half2float(hp[c]);
        #pragma unroll
        for (int j = 0; j < NC; j++) acc[j] += xv * Ws[j * D1 + c];
    }
    #pragma unroll
    for (int j = 0; j < NC; j++) acc[j] = wredsum(acc[j]);
    if (lane == 0) {
        float s = 0.f, dd = 0.f;
        #pragma unroll
        for (int j = 0; j < NC; j++) {
            g_h2[n * NC + j] = acc[j];
            s  += acc[j] * sas[j];
            dd += acc[j] * sad[j];
        }
        g_asrc2[n] = s;
        g_adst2[n] = dd;
    }
}

// -------- layer-2 edge softmax + aggregation (warp per dst, single pass) --------
__global__ void agg2_kernel(const float* __restrict__ b2) {
    int n = blockIdx.x * 8 + (threadIdx.x >> 5);
    if (n >= NN) return;
    int lane = threadIdx.x & 31;
    int beg = g_rowptr[n], end = g_rowptr[n + 1];
    float adv = g_adst2[n];
    float s = 0.f;
    float acc[NC];
    #pragma unroll
    for (int j = 0; j < NC; j++) acc[j] = 0.f;
    for (int i = beg + lane; i < end; i += 32) {
        int sn = g_csrc[i];
        float e = g_asrc2[sn] + adv;
        e = e > 0.f ? e : 0.2f * e;
        float w = __expf(e);
        s += w;
        const float* hp = &g_h2[sn * NC];
        #pragma unroll
        for (int j = 0; j < NC; j++) acc[j] += w * hp[j];
    }
    s = wredsum(s);
    #pragma unroll
    for (int j = 0; j < NC; j++) acc[j] = wredsum(acc[j]);
    if (lane == 0) {
        float inv = 1.f / (s + 1e-16f);
        #pragma unroll
        for (int j = 0; j < NC; j++)
            g_agg2[n * NC + j] = acc[j] * inv + b2[j];
    }
}

// -------- mean pooling per graph (batch is sorted) --------
__global__ void pool_kernel(const int* __restrict__ batch,
                            float* __restrict__ out) {
    int g = blockIdx.x;
    int t = threadIdx.x;
    int lo, hi;
    { int a = 0, b = NN;
      while (a < b) { int mid = (a + b) >> 1; if (batch[mid] < g) a = mid + 1; else b = mid; }
      lo = a; }
    { int a = lo, b = NN;
      while (a < b) { int mid = (a + b) >> 1; if (batch[mid] < g + 1) a = mid + 1; else b = mid; }
      hi = a; }
    __shared__ float red[NC];
    if (t < NC) red[t] = 0.f;
    __syncthreads();
    float acc[NC];
    #pragma unroll
    for (int j = 0; j < NC; j++) acc[j] = 0.f;
    for (int i = lo + t; i < hi; i += 256) {
        const float* hp = &g_agg2[i * NC];
        #pragma unroll
        for (int j = 0; j < NC; j++) acc[j] += hp[j];
    }
    #pragma unroll
    for (int j = 0; j < NC; j++) atomicAdd(&red[j], acc[j]);
    __syncthreads();
    int cnt = hi - lo;
    if (cnt < 1) cnt = 1;
    if (t < NC) out[g * NC + t] = red[t] / (float)cnt;
}

// -------- launcher (gemm1_tc at launch idx 3 for profiling) --------
extern "C" void kernel_launch(void* const* d_in, const int* in_sizes, int n_in,
                              void* d_out, int out_size) {
    const float* x   = (const float*)d_in[0];
    const int*   ei  = (const int*)d_in[1];
    const int*   bat = (const int*)d_in[2];
    const float* W1  = (const float*)d_in[3];
    const float* as1 = (const float*)d_in[4];
    const float* ad1 = (const float*)d_in[5];
    const float* b1  = (const float*)d_in[6];
    const float* W2  = (const float*)d_in[7];
    const float* as2 = (const float*)d_in[8];
    const float* ad2 = (const float*)d_in[9];
    const float* b2  = (const float*)d_in[10];
    float* out = (float*)d_out;

    prep_kernel<<<(NN * FIN / 4 + 255) / 256, 256>>>(x, W1, ei);
    scanA_kernel<<<NB, 256>>>();
    scanB_kernel<<<1, 128>>>();
    gemm1_tc_kernel<<<dim3(HEADS, (NN + 127) / 128), 256>>>(as1, ad1);
    scanC_kernel<<<(NN + 255) / 256, 256>>>();
    scatter_ew_kernel<<<(EE / 4 + 255) / 256, 256>>>(ei);

    agg1_kernel<<<NN / 2, 256>>>(b1);

    node2_kernel<<<(NN + 7) / 8, 256>>>(W2, as2, ad2);
    agg2_kernel<<<(NN + 7) / 8, 256>>>(b2);
    pool_kernel<<<NG, 256>>>(bat, out);
}